// round 4
// baseline (speedup 1.0000x reference)
#include <cuda_runtime.h>
#include <cuda_bf16.h>
#include <cstdint>

#define NB   32
#define HWD  128
#define CONDD 256
#define HIDD 4608
#define NPARAM 9216
#define KSPLIT 8
#define KCHUNK 576             // HIDD / KSPLIT

// Scratch (device globals: allocation-free rule)
__device__ float g_ht[HIDD * NB];
__device__ float g_part[KSPLIT * NB * NPARAM];
// per-sample conv weights, bf16 hi/lo split: [b][half][co 32][k 296 padded]
#define WB_ROW   296
#define WB_ELEMS (2 * 32 * WB_ROW)          // 18944 per sample
__device__ __align__(16) __nv_bfloat16 g_wb[NB * WB_ELEMS];

typedef unsigned long long u64;

// ---------------------------------------------------------------------------
// f32x2 helpers (gemm2 only)
// ---------------------------------------------------------------------------
__device__ __forceinline__ u64 pack2(float lo, float hi) {
    u64 r; asm("mov.b64 %0, {%1, %2};" : "=l"(r) : "f"(lo), "f"(hi)); return r;
}
__device__ __forceinline__ u64 splat2(float v) { return pack2(v, v); }
__device__ __forceinline__ u64 fma2(u64 a, u64 b, u64 c) {
    u64 d; asm("fma.rn.f32x2 %0, %1, %2, %3;" : "=l"(d) : "l"(a), "l"(b), "l"(c));
    return d;
}
__device__ __forceinline__ float2 unpack2(u64 v) {
    float2 r; asm("mov.b64 {%0, %1}, %2;" : "=f"(r.x), "=f"(r.y) : "l"(v));
    return r;
}

__device__ __forceinline__ uint32_t smem_to_u32(const void* p) {
    uint32_t a;
    asm("{ .reg .u64 t; cvta.to.shared.u64 t, %1; cvt.u32.u64 %0, t; }"
        : "=r"(a) : "l"(p));
    return a;
}

// ---------------------------------------------------------------------------
// warp-mma helpers (sm_80+ features: work on plain sm_103 target)
// ---------------------------------------------------------------------------
__device__ __forceinline__ void ldsm_x4(uint32_t r[4], uint32_t addr) {
    asm volatile("ldmatrix.sync.aligned.m8n8.x4.shared.b16 {%0,%1,%2,%3}, [%4];"
        : "=r"(r[0]), "=r"(r[1]), "=r"(r[2]), "=r"(r[3]) : "r"(addr));
}
__device__ __forceinline__ void mma_bf16(float d[4], const uint32_t a[4],
                                         uint32_t b0, uint32_t b1) {
    asm volatile(
        "mma.sync.aligned.m16n8k16.row.col.f32.bf16.bf16.f32 "
        "{%0,%1,%2,%3}, {%4,%5,%6,%7}, {%8,%9}, {%0,%1,%2,%3};"
        : "+f"(d[0]), "+f"(d[1]), "+f"(d[2]), "+f"(d[3])
        : "r"(a[0]), "r"(a[1]), "r"(a[2]), "r"(a[3]), "r"(b0), "r"(b1));
}

// ---------------------------------------------------------------------------
// Kernel 1: h = relu(cond @ W1^T + b1) -> ht[hid][b]
// ---------------------------------------------------------------------------
__global__ void mlp1_kernel(const float* __restrict__ cond,
                            const float* __restrict__ W1,
                            const float* __restrict__ b1) {
    int idx = blockIdx.x * blockDim.x + threadIdx.x;
    int hid = idx >> 5;
    int b   = idx & 31;
    const float4* c4 = (const float4*)(cond + b * CONDD);
    const float4* w4 = (const float4*)(W1 + (size_t)hid * CONDD);
    float acc = b1[hid];
#pragma unroll 8
    for (int i = 0; i < CONDD / 4; i++) {
        float4 cv = c4[i]; float4 wv = w4[i];
        acc += cv.x * wv.x + cv.y * wv.y + cv.z * wv.z + cv.w * wv.w;
    }
    g_ht[hid * 32 + b] = fmaxf(acc, 0.0f);
}

// ---------------------------------------------------------------------------
// Kernel 2: gemm2 k-split partials (f32x2, KSPLIT=8) — unchanged from R2
// ---------------------------------------------------------------------------
__global__ void gemm2_kernel(const float* __restrict__ W2) {
    __shared__ float s_h[32 * 32];
    __shared__ float s_w[32 * 132];

    int t = threadIdx.x;
    int pbase = blockIdx.x * 128;
    int kc    = blockIdx.y;
    int b0 = (t & 7) * 4;
    int p0 = (t >> 3) * 4;

    u64 acc2[4][2];
#pragma unroll
    for (int i = 0; i < 4; i++) { acc2[i][0] = 0; acc2[i][1] = 0; }

    const float4* ht4 = (const float4*)g_ht;
    const float4* W24 = (const float4*)W2;

    int lh_k = t >> 3, lh_c4 = t & 7;
    int lw_p[4], lw_k4[4];
#pragma unroll
    for (int i = 0; i < 4; i++) {
        int j = t + i * 256; lw_p[i] = j >> 3; lw_k4[i] = j & 7;
    }

    int kbase = kc * KCHUNK;
    float4 rh = ht4[(kbase + lh_k) * 8 + lh_c4];
    float4 rw[4];
#pragma unroll
    for (int i = 0; i < 4; i++)
        rw[i] = W24[(size_t)(pbase + lw_p[i]) * 1152 + (kbase >> 2) + lw_k4[i]];

    for (int ks = 0; ks < KCHUNK; ks += 32) {
        __syncthreads();
        ((float4*)s_h)[t] = rh;
#pragma unroll
        for (int i = 0; i < 4; i++) {
            int p = lw_p[i], k4 = lw_k4[i];
            s_w[(k4 * 4 + 0) * 132 + p] = rw[i].x;
            s_w[(k4 * 4 + 1) * 132 + p] = rw[i].y;
            s_w[(k4 * 4 + 2) * 132 + p] = rw[i].z;
            s_w[(k4 * 4 + 3) * 132 + p] = rw[i].w;
        }
        __syncthreads();

        if (ks + 32 < KCHUNK) {
            int kn = kc * KCHUNK + ks + 32;
            rh = ht4[(kn + lh_k) * 8 + lh_c4];
#pragma unroll
            for (int i = 0; i < 4; i++)
                rw[i] = W24[(size_t)(pbase + lw_p[i]) * 1152 + (kn >> 2) + lw_k4[i]];
        }

#pragma unroll
        for (int kk = 0; kk < 32; kk++) {
            float4 hv = *(const float4*)&s_h[kk * 32 + b0];
            u64 w01 = *(const u64*)&s_w[kk * 132 + p0];
            u64 w23 = *(const u64*)&s_w[kk * 132 + p0 + 2];
            u64 hs0 = splat2(hv.x), hs1 = splat2(hv.y);
            u64 hs2 = splat2(hv.z), hs3 = splat2(hv.w);
            acc2[0][0] = fma2(hs0, w01, acc2[0][0]);
            acc2[0][1] = fma2(hs0, w23, acc2[0][1]);
            acc2[1][0] = fma2(hs1, w01, acc2[1][0]);
            acc2[1][1] = fma2(hs1, w23, acc2[1][1]);
            acc2[2][0] = fma2(hs2, w01, acc2[2][0]);
            acc2[2][1] = fma2(hs2, w23, acc2[2][1]);
            acc2[3][0] = fma2(hs3, w01, acc2[3][0]);
            acc2[3][1] = fma2(hs3, w23, acc2[3][1]);
        }
    }

    float* dst = g_part + (size_t)kc * (NB * NPARAM);
#pragma unroll
    for (int i = 0; i < 4; i++) {
        float2 lo = unpack2(acc2[i][0]);
        float2 hi = unpack2(acc2[i][1]);
        *(float4*)&dst[(size_t)(b0 + i) * NPARAM + pbase + p0] =
            make_float4(lo.x, lo.y, hi.x, hi.y);
    }
}

// ---------------------------------------------------------------------------
// Kernel 3: reduce partials + bias, split to bf16 hi/lo, layout [b][half][co][k]
// k = (ky*3+kx)*32 + cin, row padded to 296.
// ---------------------------------------------------------------------------
__global__ void reduce_kernel(const float* __restrict__ b2) {
    int idx = blockIdx.x * blockDim.x + threadIdx.x;   // < 294912
    const int n = NB * NPARAM;
    int b = idx / NPARAM, p = idx - b * NPARAM;
    float s = b2[p];
#pragma unroll
    for (int kc = 0; kc < KSPLIT; kc++) s += g_part[idx + kc * n];

    int co = p / 288;       int r  = p - co * 288;
    int cin = r / 9;        int rr = r - cin * 9;
    int ky = rr / 3;        int kx = rr - ky * 3;
    int k  = (ky * 3 + kx) * 32 + cin;

    __nv_bfloat16 hi = __float2bfloat16(s);
    __nv_bfloat16 lo = __float2bfloat16(s - __bfloat162float(hi));

    __nv_bfloat16* dst = g_wb + (size_t)b * WB_ELEMS;
    dst[(0 * 32 + co) * WB_ROW + k] = hi;
    dst[(1 * 32 + co) * WB_ROW + k] = lo;
}

// ---------------------------------------------------------------------------
// Kernel 4: warp-mma conv. CTA = (b, 8 out rows, 64 out cols), 8 warps (one
// out-row each), 4 mtiles x 4 ntiles of m16n8k16, K = 9(ky,kx) x 32cin x
// {hh, hl, lh} passes. x-tile smem: [10y][66x][cin pad 40] bf16, hi & lo.
// ---------------------------------------------------------------------------
#define XT_XS 40                 // cin stride (elems) per x — bank-safe pad
#define XT_YS (66 * XT_XS)       // 2640 elems
#define XT_ELEMS (10 * XT_YS)    // 26400 elems = 52800 B
#define XT_BYTES (XT_ELEMS * 2)
#define SB_ROWB (WB_ROW * 2)     // 592 B per co row
#define SB_BYTES (32 * SB_ROWB)  // 18944 B per half
#define CONV_SMEM (2 * XT_BYTES + 2 * SB_BYTES)   // 143488 B

__global__ void __launch_bounds__(256, 1)
conv_kernel(const float* __restrict__ x, float* __restrict__ out) {
    extern __shared__ unsigned char smem[];
    __nv_bfloat16* s_xhi = (__nv_bfloat16*)smem;
    __nv_bfloat16* s_xlo = (__nv_bfloat16*)(smem + XT_BYTES);
    uint4*         s_b4  = (uint4*)(smem + 2 * XT_BYTES);

    int t = threadIdx.x, lane = t & 31, w = t >> 5;
    int b   = blockIdx.z;
    int y0  = blockIdx.y * 8;
    int x0g = blockIdx.x * 64;

    // ---- B copy (pre-split, pre-laid-out) ----
    {
        const uint4* src = (const uint4*)(g_wb + (size_t)b * WB_ELEMS);
        for (int i = t; i < (2 * SB_BYTES) / 16; i += 256) s_b4[i] = src[i];
    }

    // ---- x tile: [y 0..9][x 0..65][cin], bf16 hi/lo ----
    for (int pp = w; pp < 320; pp += 8) {        // pp = cin*10 + y
        int cin = pp / 10, y = pp - cin * 10;
        int gy = y0 - 1 + y;
        bool yv = (gy >= 0) && (gy < HWD);
        const float* row = x + (((size_t)b * 32 + cin) * HWD + gy) * HWD;
        for (int xx = lane; xx < 66; xx += 32) {
            int gx = x0g - 1 + xx;
            float v = (yv && gx >= 0 && gx < HWD) ? row[gx] : 0.0f;
            __nv_bfloat16 hi = __float2bfloat16(v);
            __nv_bfloat16 lo = __float2bfloat16(v - __bfloat162float(hi));
            int off = y * XT_YS + xx * XT_XS + cin;
            s_xhi[off] = hi;
            s_xlo[off] = lo;
        }
    }
    __syncthreads();

    uint32_t XHI = smem_to_u32(smem);
    uint32_t XLO = XHI + XT_BYTES;
    uint32_t BHI = XHI + 2 * XT_BYTES;
    uint32_t BLO = BHI + SB_BYTES;

    // lane-dependent ldmatrix address parts
    uint32_t aoff = (uint32_t)(lane & 15) * (XT_XS * 2) +
                    (uint32_t)(lane >> 4) * 16u;          // row = x, k8 half
    uint32_t boff = (uint32_t)((((lane >> 4) & 1) * 8) + (lane & 7)) * SB_ROWB +
                    (uint32_t)((lane >> 3) & 1) * 16u;    // row = co, k8 half

    uint32_t AB[3] = {XHI, XHI, XLO};
    uint32_t BB[3] = {BHI, BLO, BHI};

    float d[4][4][4];
#pragma unroll
    for (int i = 0; i < 4; i++)
#pragma unroll
        for (int j = 0; j < 4; j++)
#pragma unroll
            for (int c = 0; c < 4; c++) d[i][j][c] = 0.0f;

    for (int p = 0; p < 3; p++) {
        uint32_t abase = AB[p] + aoff + (uint32_t)w * (XT_YS * 2);
        uint32_t bbase = BB[p] + boff;
        for (int q = 0; q < 9; q++) {
            int ky = q / 3, kx = q - ky * 3;
            uint32_t aq = abase + (uint32_t)ky * (XT_YS * 2) +
                          (uint32_t)kx * (XT_XS * 2);
            uint32_t bq = bbase + (uint32_t)q * 64u;
#pragma unroll
            for (int h = 0; h < 2; h++) {
                uint32_t A[4][4];
#pragma unroll
                for (int i = 0; i < 4; i++)
                    ldsm_x4(A[i], aq + h * 32u + (uint32_t)i * (16 * XT_XS * 2));
                uint32_t B0[4], B1[4];
                ldsm_x4(B0, bq + h * 32u);
                ldsm_x4(B1, bq + h * 32u + 16u * SB_ROWB);
#pragma unroll
                for (int i = 0; i < 4; i++) {
                    mma_bf16(d[i][0], A[i], B0[0], B0[1]);
                    mma_bf16(d[i][1], A[i], B0[2], B0[3]);
                    mma_bf16(d[i][2], A[i], B1[0], B1[1]);
                    mma_bf16(d[i][3], A[i], B1[2], B1[3]);
                }
            }
        }
    }

    // ---- epilogue: D frag (row = x offset, col = co offset) -> out ----
    int g  = lane >> 2;
    int tg = lane & 3;
    int yo = y0 + w;
#pragma unroll
    for (int i = 0; i < 4; i++) {
        int xo = x0g + i * 16 + g;
#pragma unroll
        for (int j = 0; j < 4; j++) {
            int co = j * 8 + tg * 2;
            float* p0 = out + (((size_t)(b * 32 + co)) * HWD + yo) * HWD + xo;
            p0[0]             = d[i][j][0];
            p0[HWD * HWD]     = d[i][j][1];
            p0[8]             = d[i][j][2];
            p0[HWD * HWD + 8] = d[i][j][3];
        }
    }
}

// ---------------------------------------------------------------------------
extern "C" void kernel_launch(void* const* d_in, const int* in_sizes, int n_in,
                              void* d_out, int out_size) {
    const float* x    = (const float*)d_in[0];
    const float* cond = (const float*)d_in[1];
    const float* W1   = (const float*)d_in[2];
    const float* b1   = (const float*)d_in[3];
    const float* W2   = (const float*)d_in[4];
    const float* b2   = (const float*)d_in[5];
    float* out = (float*)d_out;

    cudaFuncSetAttribute(conv_kernel,
                         cudaFuncAttributeMaxDynamicSharedMemorySize, CONV_SMEM);

    mlp1_kernel<<<(HIDD * NB) / 256, 256>>>(cond, W1, b1);
    gemm2_kernel<<<dim3(NPARAM / 128, KSPLIT), 256>>>(W2);
    reduce_kernel<<<(NB * NPARAM) / 256, 256>>>(b2);
    conv_kernel<<<dim3(2, 16, NB), 256, CONV_SMEM>>>(x, out);
}

// round 5
// speedup vs baseline: 1.5380x; 1.5380x over previous
#include <cuda_runtime.h>
#include <cuda_bf16.h>
#include <cstdint>

#define NB   32
#define HWD  128
#define CONDD 256
#define HIDD 4608
#define NPARAM 9216
#define KSPLIT 8
#define KCHUNK 576             // HIDD / KSPLIT

// Scratch (device globals: allocation-free rule)
__device__ float g_ht[HIDD * NB];
__device__ float g_part[KSPLIT * NB * NPARAM];
// per-sample conv weights, bf16 hi/lo split: [b][half][co 32][k 296 padded]
#define WB_ROW   296
#define WB_ELEMS (2 * 32 * WB_ROW)          // 18944 per sample
__device__ __align__(16) __nv_bfloat16 g_wb[NB * WB_ELEMS];

typedef unsigned long long u64;

// ---------------------------------------------------------------------------
// f32x2 helpers (gemm2 only)
// ---------------------------------------------------------------------------
__device__ __forceinline__ u64 pack2(float lo, float hi) {
    u64 r; asm("mov.b64 %0, {%1, %2};" : "=l"(r) : "f"(lo), "f"(hi)); return r;
}
__device__ __forceinline__ u64 splat2(float v) { return pack2(v, v); }
__device__ __forceinline__ u64 fma2(u64 a, u64 b, u64 c) {
    u64 d; asm("fma.rn.f32x2 %0, %1, %2, %3;" : "=l"(d) : "l"(a), "l"(b), "l"(c));
    return d;
}
__device__ __forceinline__ float2 unpack2(u64 v) {
    float2 r; asm("mov.b64 {%0, %1}, %2;" : "=f"(r.x), "=f"(r.y) : "l"(v));
    return r;
}

__device__ __forceinline__ uint32_t smem_to_u32(const void* p) {
    uint32_t a;
    asm("{ .reg .u64 t; cvta.to.shared.u64 t, %1; cvt.u32.u64 %0, t; }"
        : "=r"(a) : "l"(p));
    return a;
}

// ---------------------------------------------------------------------------
// warp-mma helpers (sm_80+ features: valid on plain sm_103 target)
// ---------------------------------------------------------------------------
__device__ __forceinline__ void ldsm_x4(uint32_t r[4], uint32_t addr) {
    asm volatile("ldmatrix.sync.aligned.m8n8.x4.shared.b16 {%0,%1,%2,%3}, [%4];"
        : "=r"(r[0]), "=r"(r[1]), "=r"(r[2]), "=r"(r[3]) : "r"(addr));
}
__device__ __forceinline__ void mma_bf16(float d[4], const uint32_t a[4],
                                         uint32_t b0, uint32_t b1) {
    asm volatile(
        "mma.sync.aligned.m16n8k16.row.col.f32.bf16.bf16.f32 "
        "{%0,%1,%2,%3}, {%4,%5,%6,%7}, {%8,%9}, {%0,%1,%2,%3};"
        : "+f"(d[0]), "+f"(d[1]), "+f"(d[2]), "+f"(d[3])
        : "r"(a[0]), "r"(a[1]), "r"(a[2]), "r"(a[3]), "r"(b0), "r"(b1));
}

// ---------------------------------------------------------------------------
// Kernel 1: h = relu(cond @ W1^T + b1) -> ht[hid][b]
// ---------------------------------------------------------------------------
__global__ void mlp1_kernel(const float* __restrict__ cond,
                            const float* __restrict__ W1,
                            const float* __restrict__ b1) {
    int idx = blockIdx.x * blockDim.x + threadIdx.x;
    int hid = idx >> 5;
    int b   = idx & 31;
    const float4* c4 = (const float4*)(cond + b * CONDD);
    const float4* w4 = (const float4*)(W1 + (size_t)hid * CONDD);
    float acc = b1[hid];
#pragma unroll 8
    for (int i = 0; i < CONDD / 4; i++) {
        float4 cv = c4[i]; float4 wv = w4[i];
        acc += cv.x * wv.x + cv.y * wv.y + cv.z * wv.z + cv.w * wv.w;
    }
    g_ht[hid * 32 + b] = fmaxf(acc, 0.0f);
}

// ---------------------------------------------------------------------------
// Kernel 2: gemm2 k-split partials (f32x2, KSPLIT=8)
// ---------------------------------------------------------------------------
__global__ void gemm2_kernel(const float* __restrict__ W2) {
    __shared__ float s_h[32 * 32];
    __shared__ float s_w[32 * 132];

    int t = threadIdx.x;
    int pbase = blockIdx.x * 128;
    int kc    = blockIdx.y;
    int b0 = (t & 7) * 4;
    int p0 = (t >> 3) * 4;

    u64 acc2[4][2];
#pragma unroll
    for (int i = 0; i < 4; i++) { acc2[i][0] = 0; acc2[i][1] = 0; }

    const float4* ht4 = (const float4*)g_ht;
    const float4* W24 = (const float4*)W2;

    int lh_k = t >> 3, lh_c4 = t & 7;
    int lw_p[4], lw_k4[4];
#pragma unroll
    for (int i = 0; i < 4; i++) {
        int j = t + i * 256; lw_p[i] = j >> 3; lw_k4[i] = j & 7;
    }

    int kbase = kc * KCHUNK;
    float4 rh = ht4[(kbase + lh_k) * 8 + lh_c4];
    float4 rw[4];
#pragma unroll
    for (int i = 0; i < 4; i++)
        rw[i] = W24[(size_t)(pbase + lw_p[i]) * 1152 + (kbase >> 2) + lw_k4[i]];

    for (int ks = 0; ks < KCHUNK; ks += 32) {
        __syncthreads();
        ((float4*)s_h)[t] = rh;
#pragma unroll
        for (int i = 0; i < 4; i++) {
            int p = lw_p[i], k4 = lw_k4[i];
            s_w[(k4 * 4 + 0) * 132 + p] = rw[i].x;
            s_w[(k4 * 4 + 1) * 132 + p] = rw[i].y;
            s_w[(k4 * 4 + 2) * 132 + p] = rw[i].z;
            s_w[(k4 * 4 + 3) * 132 + p] = rw[i].w;
        }
        __syncthreads();

        if (ks + 32 < KCHUNK) {
            int kn = kc * KCHUNK + ks + 32;
            rh = ht4[(kn + lh_k) * 8 + lh_c4];
#pragma unroll
            for (int i = 0; i < 4; i++)
                rw[i] = W24[(size_t)(pbase + lw_p[i]) * 1152 + (kn >> 2) + lw_k4[i]];
        }

#pragma unroll
        for (int kk = 0; kk < 32; kk++) {
            float4 hv = *(const float4*)&s_h[kk * 32 + b0];
            u64 w01 = *(const u64*)&s_w[kk * 132 + p0];
            u64 w23 = *(const u64*)&s_w[kk * 132 + p0 + 2];
            u64 hs0 = splat2(hv.x), hs1 = splat2(hv.y);
            u64 hs2 = splat2(hv.z), hs3 = splat2(hv.w);
            acc2[0][0] = fma2(hs0, w01, acc2[0][0]);
            acc2[0][1] = fma2(hs0, w23, acc2[0][1]);
            acc2[1][0] = fma2(hs1, w01, acc2[1][0]);
            acc2[1][1] = fma2(hs1, w23, acc2[1][1]);
            acc2[2][0] = fma2(hs2, w01, acc2[2][0]);
            acc2[2][1] = fma2(hs2, w23, acc2[2][1]);
            acc2[3][0] = fma2(hs3, w01, acc2[3][0]);
            acc2[3][1] = fma2(hs3, w23, acc2[3][1]);
        }
    }

    float* dst = g_part + (size_t)kc * (NB * NPARAM);
#pragma unroll
    for (int i = 0; i < 4; i++) {
        float2 lo = unpack2(acc2[i][0]);
        float2 hi = unpack2(acc2[i][1]);
        *(float4*)&dst[(size_t)(b0 + i) * NPARAM + pbase + p0] =
            make_float4(lo.x, lo.y, hi.x, hi.y);
    }
}

// ---------------------------------------------------------------------------
// Kernel 3: reduce partials + bias, split to bf16 hi/lo, layout [b][half][co][k]
// ---------------------------------------------------------------------------
__global__ void reduce_kernel(const float* __restrict__ b2) {
    int idx = blockIdx.x * blockDim.x + threadIdx.x;   // < 294912
    const int n = NB * NPARAM;
    int b = idx / NPARAM, p = idx - b * NPARAM;
    float s = b2[p];
#pragma unroll
    for (int kc = 0; kc < KSPLIT; kc++) s += g_part[idx + kc * n];

    int co = p / 288;       int r  = p - co * 288;
    int cin = r / 9;        int rr = r - cin * 9;
    int ky = rr / 3;        int kx = rr - ky * 3;
    int k  = (ky * 3 + kx) * 32 + cin;

    __nv_bfloat16 hi = __float2bfloat16(s);
    __nv_bfloat16 lo = __float2bfloat16(s - __bfloat162float(hi));

    __nv_bfloat16* dst = g_wb + (size_t)b * WB_ELEMS;
    dst[(0 * 32 + co) * WB_ROW + k] = hi;
    dst[(1 * 32 + co) * WB_ROW + k] = lo;
}

// ---------------------------------------------------------------------------
// Kernel 4: warp-mma conv. CTA = (b, 8 out rows, 64 out cols), 512 threads =
// 16 warps: warp = (y-row, x-half of 32 cols). Per warp: 2 mtiles x 4 ntiles
// m16n8k16; K = 3 passes{hh,hl,lh} x 9(ky,kx) x 2 k16-chunks of cin.
// ---------------------------------------------------------------------------
#define XT_XS 40                 // cin stride (elems) per x — bank-safe pad
#define XT_YS (66 * XT_XS)       // 2640 elems
#define XT_ELEMS (10 * XT_YS)    // 26400 elems
#define XT_BYTES (XT_ELEMS * 2)
#define SB_ROWB (WB_ROW * 2)     // 592 B per co row
#define SB_BYTES (32 * SB_ROWB)  // 18944 B per half
#define CONV_SMEM (2 * XT_BYTES + 2 * SB_BYTES)   // 143488 B

__global__ void __launch_bounds__(512, 1)
conv_kernel(const float* __restrict__ x, float* __restrict__ out) {
    extern __shared__ unsigned char smem[];
    __nv_bfloat16* s_xhi = (__nv_bfloat16*)smem;
    __nv_bfloat16* s_xlo = (__nv_bfloat16*)(smem + XT_BYTES);
    uint4*         s_b4  = (uint4*)(smem + 2 * XT_BYTES);

    int t = threadIdx.x, lane = t & 31, w = t >> 5;
    int b   = blockIdx.z;
    int y0  = blockIdx.y * 8;
    int x0g = blockIdx.x * 64;

    // ---- B copy (pre-split, pre-laid-out) ----
    {
        const uint4* src = (const uint4*)(g_wb + (size_t)b * WB_ELEMS);
        for (int i = t; i < (2 * SB_BYTES) / 16; i += 512) s_b4[i] = src[i];
    }

    // ---- x tile: [y 0..9][x 0..65][cin], bf16 hi/lo ----
    for (int pp = w; pp < 320; pp += 16) {       // pp = cin*10 + y
        int cin = pp / 10, y = pp - cin * 10;
        int gy = y0 - 1 + y;
        bool yv = (gy >= 0) && (gy < HWD);
        const float* row = x + (((size_t)b * 32 + cin) * HWD + gy) * HWD;
        for (int xx = lane; xx < 66; xx += 32) {
            int gx = x0g - 1 + xx;
            float v = (yv && gx >= 0 && gx < HWD) ? row[gx] : 0.0f;
            __nv_bfloat16 hi = __float2bfloat16(v);
            __nv_bfloat16 lo = __float2bfloat16(v - __bfloat162float(hi));
            int off = y * XT_YS + xx * XT_XS + cin;
            s_xhi[off] = hi;
            s_xlo[off] = lo;
        }
    }
    __syncthreads();

    uint32_t XHI = smem_to_u32(smem);
    uint32_t XLO = XHI + XT_BYTES;
    uint32_t BHI = XHI + 2 * XT_BYTES;
    uint32_t BLO = BHI + SB_BYTES;

    int yw = w >> 1;             // out row within slab (0..7)
    int xh = w & 1;              // x half (0..1), 32 cols each

    // lane-dependent ldmatrix address parts (same mapping as validated R4)
    uint32_t aoff = (uint32_t)(lane & 15) * (XT_XS * 2) +
                    (uint32_t)(lane >> 4) * 16u;          // row = x, k8 half
    uint32_t boff = (uint32_t)((((lane >> 4) & 1) * 8) + (lane & 7)) * SB_ROWB +
                    (uint32_t)((lane >> 3) & 1) * 16u;    // row = co, k8 half

    uint32_t AB[3] = {XHI, XHI, XLO};
    uint32_t BB[3] = {BHI, BLO, BHI};

    float d[2][4][4];
#pragma unroll
    for (int i = 0; i < 2; i++)
#pragma unroll
        for (int j = 0; j < 4; j++)
#pragma unroll
            for (int c = 0; c < 4; c++) d[i][j][c] = 0.0f;

    // warp's A base: row offset = yw (y) and xh*32 (x)
    uint32_t awarp = aoff + (uint32_t)yw * (XT_YS * 2) +
                     (uint32_t)xh * (32 * XT_XS * 2);

#pragma unroll
    for (int p = 0; p < 3; p++) {
        uint32_t abase = AB[p] + awarp;
        uint32_t bbase = BB[p] + boff;
#pragma unroll 3
        for (int q = 0; q < 9; q++) {
            int ky = q / 3, kx = q - ky * 3;
            uint32_t aq = abase + (uint32_t)ky * (XT_YS * 2) +
                          (uint32_t)kx * (XT_XS * 2);
            uint32_t bq = bbase + (uint32_t)q * 64u;
#pragma unroll
            for (int h = 0; h < 2; h++) {
                uint32_t A0[4], A1[4], B0[4], B1[4];
                ldsm_x4(A0, aq + h * 32u);
                ldsm_x4(A1, aq + h * 32u + (16 * XT_XS * 2));
                ldsm_x4(B0, bq + h * 32u);
                ldsm_x4(B1, bq + h * 32u + 16u * SB_ROWB);
                mma_bf16(d[0][0], A0, B0[0], B0[1]);
                mma_bf16(d[0][1], A0, B0[2], B0[3]);
                mma_bf16(d[0][2], A0, B1[0], B1[1]);
                mma_bf16(d[0][3], A0, B1[2], B1[3]);
                mma_bf16(d[1][0], A1, B0[0], B0[1]);
                mma_bf16(d[1][1], A1, B0[2], B0[3]);
                mma_bf16(d[1][2], A1, B1[0], B1[1]);
                mma_bf16(d[1][3], A1, B1[2], B1[3]);
            }
        }
    }

    // ---- epilogue: D frag (row = x offset, col = co offset) -> out ----
    int g  = lane >> 2;
    int tg = lane & 3;
    int yo = y0 + yw;
#pragma unroll
    for (int i = 0; i < 2; i++) {
        int xo = x0g + xh * 32 + i * 16 + g;
#pragma unroll
        for (int j = 0; j < 4; j++) {
            int co = j * 8 + tg * 2;
            float* p0 = out + (((size_t)(b * 32 + co)) * HWD + yo) * HWD + xo;
            p0[0]             = d[i][j][0];
            p0[HWD * HWD]     = d[i][j][1];
            p0[8]             = d[i][j][2];
            p0[HWD * HWD + 8] = d[i][j][3];
        }
    }
}

// ---------------------------------------------------------------------------
extern "C" void kernel_launch(void* const* d_in, const int* in_sizes, int n_in,
                              void* d_out, int out_size) {
    const float* x    = (const float*)d_in[0];
    const float* cond = (const float*)d_in[1];
    const float* W1   = (const float*)d_in[2];
    const float* b1   = (const float*)d_in[3];
    const float* W2   = (const float*)d_in[4];
    const float* b2   = (const float*)d_in[5];
    float* out = (float*)d_out;

    cudaFuncSetAttribute(conv_kernel,
                         cudaFuncAttributeMaxDynamicSharedMemorySize, CONV_SMEM);

    mlp1_kernel<<<(HIDD * NB) / 256, 256>>>(cond, W1, b1);
    gemm2_kernel<<<dim3(NPARAM / 128, KSPLIT), 256>>>(W2);
    reduce_kernel<<<(NB * NPARAM) / 256, 256>>>(b2);
    conv_kernel<<<dim3(2, 16, NB), 512, CONV_SMEM>>>(x, out);
}

// round 6
// speedup vs baseline: 1.9191x; 1.2478x over previous
#include <cuda_runtime.h>
#include <cuda_bf16.h>
#include <cstdint>

#define NB   32
#define HWD  128
#define CONDD 256
#define HIDD 4608
#define NPARAM 9216
#define KSPLIT 16
#define KCHUNK 288             // HIDD / KSPLIT

// Scratch (device globals: allocation-free rule)
__device__ float g_ht[HIDD * NB];
__device__ float g_part[KSPLIT * NB * NPARAM];
// per-sample conv weights, bf16 hi/lo split: [b][half][co 32][k 296 padded]
#define WB_ROW   296
#define WB_ELEMS (2 * 32 * WB_ROW)          // 18944 per sample
__device__ __align__(16) __nv_bfloat16 g_wb[NB * WB_ELEMS];

typedef unsigned long long u64;

// ---------------------------------------------------------------------------
// f32x2 helpers (gemm2 only)
// ---------------------------------------------------------------------------
__device__ __forceinline__ u64 pack2(float lo, float hi) {
    u64 r; asm("mov.b64 %0, {%1, %2};" : "=l"(r) : "f"(lo), "f"(hi)); return r;
}
__device__ __forceinline__ u64 splat2(float v) { return pack2(v, v); }
__device__ __forceinline__ u64 fma2(u64 a, u64 b, u64 c) {
    u64 d; asm("fma.rn.f32x2 %0, %1, %2, %3;" : "=l"(d) : "l"(a), "l"(b), "l"(c));
    return d;
}
__device__ __forceinline__ float2 unpack2(u64 v) {
    float2 r; asm("mov.b64 {%0, %1}, %2;" : "=f"(r.x), "=f"(r.y) : "l"(v));
    return r;
}

__device__ __forceinline__ uint32_t smem_to_u32(const void* p) {
    uint32_t a;
    asm("{ .reg .u64 t; cvta.to.shared.u64 t, %1; cvt.u32.u64 %0, t; }"
        : "=r"(a) : "l"(p));
    return a;
}

// ---------------------------------------------------------------------------
// warp-mma helpers (sm_80+ features: valid on plain sm_103 target)
// ---------------------------------------------------------------------------
__device__ __forceinline__ void ldsm_x4(uint32_t r[4], uint32_t addr) {
    asm volatile("ldmatrix.sync.aligned.m8n8.x4.shared.b16 {%0,%1,%2,%3}, [%4];"
        : "=r"(r[0]), "=r"(r[1]), "=r"(r[2]), "=r"(r[3]) : "r"(addr));
}
__device__ __forceinline__ void mma_bf16(float d[4], const uint32_t a[4],
                                         uint32_t b0, uint32_t b1) {
    asm volatile(
        "mma.sync.aligned.m16n8k16.row.col.f32.bf16.bf16.f32 "
        "{%0,%1,%2,%3}, {%4,%5,%6,%7}, {%8,%9}, {%0,%1,%2,%3};"
        : "+f"(d[0]), "+f"(d[1]), "+f"(d[2]), "+f"(d[3])
        : "r"(a[0]), "r"(a[1]), "r"(a[2]), "r"(a[3]), "r"(b0), "r"(b1));
}

// ---------------------------------------------------------------------------
// Kernel 1: h = relu(cond @ W1^T + b1) -> ht[hid][b]
// ---------------------------------------------------------------------------
__global__ void mlp1_kernel(const float* __restrict__ cond,
                            const float* __restrict__ W1,
                            const float* __restrict__ b1) {
    int idx = blockIdx.x * blockDim.x + threadIdx.x;
    int hid = idx >> 5;
    int b   = idx & 31;
    const float4* c4 = (const float4*)(cond + b * CONDD);
    const float4* w4 = (const float4*)(W1 + (size_t)hid * CONDD);
    float acc = b1[hid];
#pragma unroll 8
    for (int i = 0; i < CONDD / 4; i++) {
        float4 cv = c4[i]; float4 wv = w4[i];
        acc += cv.x * wv.x + cv.y * wv.y + cv.z * wv.z + cv.w * wv.w;
    }
    g_ht[hid * 32 + b] = fmaxf(acc, 0.0f);
}

// ---------------------------------------------------------------------------
// Kernel 2: gemm2 k-split partials (f32x2, KSPLIT=16)
// ---------------------------------------------------------------------------
__global__ void gemm2_kernel(const float* __restrict__ W2) {
    __shared__ float s_h[32 * 32];
    __shared__ float s_w[32 * 132];

    int t = threadIdx.x;
    int pbase = blockIdx.x * 128;
    int kc    = blockIdx.y;
    int b0 = (t & 7) * 4;
    int p0 = (t >> 3) * 4;

    u64 acc2[4][2];
#pragma unroll
    for (int i = 0; i < 4; i++) { acc2[i][0] = 0; acc2[i][1] = 0; }

    const float4* ht4 = (const float4*)g_ht;
    const float4* W24 = (const float4*)W2;

    int lh_k = t >> 3, lh_c4 = t & 7;
    int lw_p[4], lw_k4[4];
#pragma unroll
    for (int i = 0; i < 4; i++) {
        int j = t + i * 256; lw_p[i] = j >> 3; lw_k4[i] = j & 7;
    }

    int kbase = kc * KCHUNK;
    float4 rh = ht4[(kbase + lh_k) * 8 + lh_c4];
    float4 rw[4];
#pragma unroll
    for (int i = 0; i < 4; i++)
        rw[i] = W24[(size_t)(pbase + lw_p[i]) * 1152 + (kbase >> 2) + lw_k4[i]];

    for (int ks = 0; ks < KCHUNK; ks += 32) {
        __syncthreads();
        ((float4*)s_h)[t] = rh;
#pragma unroll
        for (int i = 0; i < 4; i++) {
            int p = lw_p[i], k4 = lw_k4[i];
            s_w[(k4 * 4 + 0) * 132 + p] = rw[i].x;
            s_w[(k4 * 4 + 1) * 132 + p] = rw[i].y;
            s_w[(k4 * 4 + 2) * 132 + p] = rw[i].z;
            s_w[(k4 * 4 + 3) * 132 + p] = rw[i].w;
        }
        __syncthreads();

        if (ks + 32 < KCHUNK) {
            int kn = kc * KCHUNK + ks + 32;
            rh = ht4[(kn + lh_k) * 8 + lh_c4];
#pragma unroll
            for (int i = 0; i < 4; i++)
                rw[i] = W24[(size_t)(pbase + lw_p[i]) * 1152 + (kn >> 2) + lw_k4[i]];
        }

#pragma unroll
        for (int kk = 0; kk < 32; kk++) {
            float4 hv = *(const float4*)&s_h[kk * 32 + b0];
            u64 w01 = *(const u64*)&s_w[kk * 132 + p0];
            u64 w23 = *(const u64*)&s_w[kk * 132 + p0 + 2];
            u64 hs0 = splat2(hv.x), hs1 = splat2(hv.y);
            u64 hs2 = splat2(hv.z), hs3 = splat2(hv.w);
            acc2[0][0] = fma2(hs0, w01, acc2[0][0]);
            acc2[0][1] = fma2(hs0, w23, acc2[0][1]);
            acc2[1][0] = fma2(hs1, w01, acc2[1][0]);
            acc2[1][1] = fma2(hs1, w23, acc2[1][1]);
            acc2[2][0] = fma2(hs2, w01, acc2[2][0]);
            acc2[2][1] = fma2(hs2, w23, acc2[2][1]);
            acc2[3][0] = fma2(hs3, w01, acc2[3][0]);
            acc2[3][1] = fma2(hs3, w23, acc2[3][1]);
        }
    }

    float* dst = g_part + (size_t)kc * (NB * NPARAM);
#pragma unroll
    for (int i = 0; i < 4; i++) {
        float2 lo = unpack2(acc2[i][0]);
        float2 hi = unpack2(acc2[i][1]);
        *(float4*)&dst[(size_t)(b0 + i) * NPARAM + pbase + p0] =
            make_float4(lo.x, lo.y, hi.x, hi.y);
    }
}

// ---------------------------------------------------------------------------
// Kernel 3: reduce partials + bias, split to bf16 hi/lo, layout [b][half][co][k]
// ---------------------------------------------------------------------------
__global__ void reduce_kernel(const float* __restrict__ b2) {
    int idx = blockIdx.x * blockDim.x + threadIdx.x;   // < 294912
    const int n = NB * NPARAM;
    int b = idx / NPARAM, p = idx - b * NPARAM;
    float s = b2[p];
#pragma unroll
    for (int kc = 0; kc < KSPLIT; kc++) s += g_part[idx + kc * n];

    int co = p / 288;       int r  = p - co * 288;
    int cin = r / 9;        int rr = r - cin * 9;
    int ky = rr / 3;        int kx = rr - ky * 3;
    int k  = (ky * 3 + kx) * 32 + cin;

    __nv_bfloat16 hi = __float2bfloat16(s);
    __nv_bfloat16 lo = __float2bfloat16(s - __bfloat162float(hi));

    __nv_bfloat16* dst = g_wb + (size_t)b * WB_ELEMS;
    dst[(0 * 32 + co) * WB_ROW + k] = hi;
    dst[(1 * 32 + co) * WB_ROW + k] = lo;
}

// ---------------------------------------------------------------------------
// Kernel 4: warp-mma conv. CTA = (b, 8 out rows, 64 out cols), 1024 threads =
// 32 warps: warp = (y-row 0..7, x-quarter 0..3 of 16 cols). Per warp:
// 1 mtile x 4 ntiles m16n8k16. Per (q,h): load Ahi/Alo/Bhi/Blo once (6 ldsm),
// issue 12 mma (hh, hl, lh passes).
// ---------------------------------------------------------------------------
#define XT_XS 40                 // cin stride (elems) per x — bank-safe pad
#define XT_YS (66 * XT_XS)       // 2640 elems
#define XT_ELEMS (10 * XT_YS)    // 26400 elems
#define XT_BYTES (XT_ELEMS * 2)
#define SB_ROWB (WB_ROW * 2)     // 592 B per co row
#define SB_BYTES (32 * SB_ROWB)  // 18944 B per half
#define CONV_SMEM (2 * XT_BYTES + 2 * SB_BYTES)   // 143488 B

__global__ void __launch_bounds__(1024, 1)
conv_kernel(const float* __restrict__ x, float* __restrict__ out) {
    extern __shared__ unsigned char smem[];
    __nv_bfloat16* s_xhi = (__nv_bfloat16*)smem;
    __nv_bfloat16* s_xlo = (__nv_bfloat16*)(smem + XT_BYTES);
    uint4*         s_b4  = (uint4*)(smem + 2 * XT_BYTES);

    int t = threadIdx.x, lane = t & 31, w = t >> 5;
    int b   = blockIdx.z;
    int y0  = blockIdx.y * 8;
    int x0g = blockIdx.x * 64;

    // ---- B copy (pre-split, pre-laid-out) ----
    {
        const uint4* src = (const uint4*)(g_wb + (size_t)b * WB_ELEMS);
        for (int i = t; i < (2 * SB_BYTES) / 16; i += 1024) s_b4[i] = src[i];
    }

    // ---- x tile: [y 0..9][x 0..65][cin], bf16 hi/lo ----
    for (int pp = w; pp < 320; pp += 32) {       // pp = cin*10 + y
        int cin = pp / 10, y = pp - cin * 10;
        int gy = y0 - 1 + y;
        bool yv = (gy >= 0) && (gy < HWD);
        const float* row = x + (((size_t)b * 32 + cin) * HWD + gy) * HWD;
        for (int xx = lane; xx < 66; xx += 32) {
            int gx = x0g - 1 + xx;
            float v = (yv && gx >= 0 && gx < HWD) ? row[gx] : 0.0f;
            __nv_bfloat16 hi = __float2bfloat16(v);
            __nv_bfloat16 lo = __float2bfloat16(v - __bfloat162float(hi));
            int off = y * XT_YS + xx * XT_XS + cin;
            s_xhi[off] = hi;
            s_xlo[off] = lo;
        }
    }
    __syncthreads();

    uint32_t XHI = smem_to_u32(smem);
    uint32_t BHI = XHI + 2 * XT_BYTES;

    int yw = w >> 2;             // out row within slab (0..7)
    int xq = w & 3;              // x quarter (0..3), 16 cols each

    // lane-dependent ldmatrix address parts (validated mapping)
    uint32_t aoff = (uint32_t)(lane & 15) * (XT_XS * 2) +
                    (uint32_t)(lane >> 4) * 16u;          // row = x, k8 half
    uint32_t boff = (uint32_t)((((lane >> 4) & 1) * 8) + (lane & 7)) * SB_ROWB +
                    (uint32_t)((lane >> 3) & 1) * 16u;    // row = co, k8 half

    float d[4][4];
#pragma unroll
    for (int j = 0; j < 4; j++)
#pragma unroll
        for (int c = 0; c < 4; c++) d[j][c] = 0.0f;

    uint32_t awarp = XHI + aoff + (uint32_t)yw * (XT_YS * 2) +
                     (uint32_t)xq * (16 * XT_XS * 2);
    uint32_t bwarp = BHI + boff;

#pragma unroll 3
    for (int q = 0; q < 9; q++) {
        int ky = q / 3, kx = q - ky * 3;
        uint32_t aq = awarp + (uint32_t)ky * (XT_YS * 2) +
                      (uint32_t)kx * (XT_XS * 2);
        uint32_t bq = bwarp + (uint32_t)q * 64u;
#pragma unroll
        for (int h = 0; h < 2; h++) {
            uint32_t Ah[4], Al[4], Bh0[4], Bh1[4], Bl0[4], Bl1[4];
            ldsm_x4(Ah, aq + h * 32u);
            ldsm_x4(Al, aq + h * 32u + XT_BYTES);
            ldsm_x4(Bh0, bq + h * 32u);
            ldsm_x4(Bh1, bq + h * 32u + 16u * SB_ROWB);
            ldsm_x4(Bl0, bq + h * 32u + SB_BYTES);
            ldsm_x4(Bl1, bq + h * 32u + SB_BYTES + 16u * SB_ROWB);
            // hh
            mma_bf16(d[0], Ah, Bh0[0], Bh0[1]);
            mma_bf16(d[1], Ah, Bh0[2], Bh0[3]);
            mma_bf16(d[2], Ah, Bh1[0], Bh1[1]);
            mma_bf16(d[3], Ah, Bh1[2], Bh1[3]);
            // hl
            mma_bf16(d[0], Ah, Bl0[0], Bl0[1]);
            mma_bf16(d[1], Ah, Bl0[2], Bl0[3]);
            mma_bf16(d[2], Ah, Bl1[0], Bl1[1]);
            mma_bf16(d[3], Ah, Bl1[2], Bl1[3]);
            // lh
            mma_bf16(d[0], Al, Bh0[0], Bh0[1]);
            mma_bf16(d[1], Al, Bh0[2], Bh0[3]);
            mma_bf16(d[2], Al, Bh1[0], Bh1[1]);
            mma_bf16(d[3], Al, Bh1[2], Bh1[3]);
        }
    }

    // ---- epilogue: D frag (row = x offset, col = co offset) -> out ----
    int g  = lane >> 2;
    int tg = lane & 3;
    int yo = y0 + yw;
    int xo = x0g + xq * 16 + g;
#pragma unroll
    for (int j = 0; j < 4; j++) {
        int co = j * 8 + tg * 2;
        float* p0 = out + (((size_t)(b * 32 + co)) * HWD + yo) * HWD + xo;
        p0[0]             = d[j][0];
        p0[HWD * HWD]     = d[j][1];
        p0[8]             = d[j][2];
        p0[HWD * HWD + 8] = d[j][3];
    }
}

// ---------------------------------------------------------------------------
extern "C" void kernel_launch(void* const* d_in, const int* in_sizes, int n_in,
                              void* d_out, int out_size) {
    const float* x    = (const float*)d_in[0];
    const float* cond = (const float*)d_in[1];
    const float* W1   = (const float*)d_in[2];
    const float* b1   = (const float*)d_in[3];
    const float* W2   = (const float*)d_in[4];
    const float* b2   = (const float*)d_in[5];
    float* out = (float*)d_out;

    cudaFuncSetAttribute(conv_kernel,
                         cudaFuncAttributeMaxDynamicSharedMemorySize, CONV_SMEM);

    mlp1_kernel<<<(HIDD * NB) / 256, 256>>>(cond, W1, b1);
    gemm2_kernel<<<dim3(NPARAM / 128, KSPLIT), 256>>>(W2);
    reduce_kernel<<<(NB * NPARAM) / 256, 256>>>(b2);
    conv_kernel<<<dim3(2, 16, NB), 1024, CONV_SMEM>>>(x, out);
}

// round 7
// speedup vs baseline: 2.1165x; 1.1029x over previous
#include <cuda_runtime.h>
#include <cuda_fp16.h>
#include <cstdint>

#define NB   32
#define HWD  128
#define CONDD 256
#define HIDD 4608
#define NPARAM 9216
#define KSPLIT 16
#define KCHUNK 288             // HIDD / KSPLIT

// Scratch (device globals: allocation-free rule)
__device__ float g_ht[HIDD * NB];
__device__ float g_part[KSPLIT * NB * NPARAM];
// per-sample conv weights, single fp16: [b][co 32][k 296 padded]
#define WB_ROW   296
#define WB_ELEMS (32 * WB_ROW)              // 9472 per sample
__device__ __align__(16) __half g_wb[NB * WB_ELEMS];

typedef unsigned long long u64;

// ---------------------------------------------------------------------------
// f32x2 helpers (gemm2 only)
// ---------------------------------------------------------------------------
__device__ __forceinline__ u64 pack2(float lo, float hi) {
    u64 r; asm("mov.b64 %0, {%1, %2};" : "=l"(r) : "f"(lo), "f"(hi)); return r;
}
__device__ __forceinline__ u64 splat2(float v) { return pack2(v, v); }
__device__ __forceinline__ u64 fma2(u64 a, u64 b, u64 c) {
    u64 d; asm("fma.rn.f32x2 %0, %1, %2, %3;" : "=l"(d) : "l"(a), "l"(b), "l"(c));
    return d;
}
__device__ __forceinline__ float2 unpack2(u64 v) {
    float2 r; asm("mov.b64 {%0, %1}, %2;" : "=f"(r.x), "=f"(r.y) : "l"(v));
    return r;
}

__device__ __forceinline__ uint32_t smem_to_u32(const void* p) {
    uint32_t a;
    asm("{ .reg .u64 t; cvta.to.shared.u64 t, %1; cvt.u32.u64 %0, t; }"
        : "=r"(a) : "l"(p));
    return a;
}

// ---------------------------------------------------------------------------
// warp-mma helpers (sm_80+ features: valid on plain sm_103 target)
// ---------------------------------------------------------------------------
__device__ __forceinline__ void ldsm_x4(uint32_t r[4], uint32_t addr) {
    asm volatile("ldmatrix.sync.aligned.m8n8.x4.shared.b16 {%0,%1,%2,%3}, [%4];"
        : "=r"(r[0]), "=r"(r[1]), "=r"(r[2]), "=r"(r[3]) : "r"(addr));
}
__device__ __forceinline__ void mma_f16(float d[4], const uint32_t a[4],
                                        uint32_t b0, uint32_t b1) {
    asm volatile(
        "mma.sync.aligned.m16n8k16.row.col.f32.f16.f16.f32 "
        "{%0,%1,%2,%3}, {%4,%5,%6,%7}, {%8,%9}, {%0,%1,%2,%3};"
        : "+f"(d[0]), "+f"(d[1]), "+f"(d[2]), "+f"(d[3])
        : "r"(a[0]), "r"(a[1]), "r"(a[2]), "r"(a[3]), "r"(b0), "r"(b1));
}

// ---------------------------------------------------------------------------
// Kernel 1: h = relu(cond @ W1^T + b1) -> ht[hid][b]
// ---------------------------------------------------------------------------
__global__ void mlp1_kernel(const float* __restrict__ cond,
                            const float* __restrict__ W1,
                            const float* __restrict__ b1) {
    int idx = blockIdx.x * blockDim.x + threadIdx.x;
    int hid = idx >> 5;
    int b   = idx & 31;
    const float4* c4 = (const float4*)(cond + b * CONDD);
    const float4* w4 = (const float4*)(W1 + (size_t)hid * CONDD);
    float acc = b1[hid];
#pragma unroll 8
    for (int i = 0; i < CONDD / 4; i++) {
        float4 cv = c4[i]; float4 wv = w4[i];
        acc += cv.x * wv.x + cv.y * wv.y + cv.z * wv.z + cv.w * wv.w;
    }
    g_ht[hid * 32 + b] = fmaxf(acc, 0.0f);
}

// ---------------------------------------------------------------------------
// Kernel 2: gemm2 k-split partials (f32x2, KSPLIT=16) — unchanged
// ---------------------------------------------------------------------------
__global__ void gemm2_kernel(const float* __restrict__ W2) {
    __shared__ float s_h[32 * 32];
    __shared__ float s_w[32 * 132];

    int t = threadIdx.x;
    int pbase = blockIdx.x * 128;
    int kc    = blockIdx.y;
    int b0 = (t & 7) * 4;
    int p0 = (t >> 3) * 4;

    u64 acc2[4][2];
#pragma unroll
    for (int i = 0; i < 4; i++) { acc2[i][0] = 0; acc2[i][1] = 0; }

    const float4* ht4 = (const float4*)g_ht;
    const float4* W24 = (const float4*)W2;

    int lh_k = t >> 3, lh_c4 = t & 7;
    int lw_p[4], lw_k4[4];
#pragma unroll
    for (int i = 0; i < 4; i++) {
        int j = t + i * 256; lw_p[i] = j >> 3; lw_k4[i] = j & 7;
    }

    int kbase = kc * KCHUNK;
    float4 rh = ht4[(kbase + lh_k) * 8 + lh_c4];
    float4 rw[4];
#pragma unroll
    for (int i = 0; i < 4; i++)
        rw[i] = W24[(size_t)(pbase + lw_p[i]) * 1152 + (kbase >> 2) + lw_k4[i]];

    for (int ks = 0; ks < KCHUNK; ks += 32) {
        __syncthreads();
        ((float4*)s_h)[t] = rh;
#pragma unroll
        for (int i = 0; i < 4; i++) {
            int p = lw_p[i], k4 = lw_k4[i];
            s_w[(k4 * 4 + 0) * 132 + p] = rw[i].x;
            s_w[(k4 * 4 + 1) * 132 + p] = rw[i].y;
            s_w[(k4 * 4 + 2) * 132 + p] = rw[i].z;
            s_w[(k4 * 4 + 3) * 132 + p] = rw[i].w;
        }
        __syncthreads();

        if (ks + 32 < KCHUNK) {
            int kn = kc * KCHUNK + ks + 32;
            rh = ht4[(kn + lh_k) * 8 + lh_c4];
#pragma unroll
            for (int i = 0; i < 4; i++)
                rw[i] = W24[(size_t)(pbase + lw_p[i]) * 1152 + (kn >> 2) + lw_k4[i]];
        }

#pragma unroll
        for (int kk = 0; kk < 32; kk++) {
            float4 hv = *(const float4*)&s_h[kk * 32 + b0];
            u64 w01 = *(const u64*)&s_w[kk * 132 + p0];
            u64 w23 = *(const u64*)&s_w[kk * 132 + p0 + 2];
            u64 hs0 = splat2(hv.x), hs1 = splat2(hv.y);
            u64 hs2 = splat2(hv.z), hs3 = splat2(hv.w);
            acc2[0][0] = fma2(hs0, w01, acc2[0][0]);
            acc2[0][1] = fma2(hs0, w23, acc2[0][1]);
            acc2[1][0] = fma2(hs1, w01, acc2[1][0]);
            acc2[1][1] = fma2(hs1, w23, acc2[1][1]);
            acc2[2][0] = fma2(hs2, w01, acc2[2][0]);
            acc2[2][1] = fma2(hs2, w23, acc2[2][1]);
            acc2[3][0] = fma2(hs3, w01, acc2[3][0]);
            acc2[3][1] = fma2(hs3, w23, acc2[3][1]);
        }
    }

    float* dst = g_part + (size_t)kc * (NB * NPARAM);
#pragma unroll
    for (int i = 0; i < 4; i++) {
        float2 lo = unpack2(acc2[i][0]);
        float2 hi = unpack2(acc2[i][1]);
        *(float4*)&dst[(size_t)(b0 + i) * NPARAM + pbase + p0] =
            make_float4(lo.x, lo.y, hi.x, hi.y);
    }
}

// ---------------------------------------------------------------------------
// Kernel 3: reduce partials + bias -> single fp16 weights [b][co][k]
// ---------------------------------------------------------------------------
__global__ void reduce_kernel(const float* __restrict__ b2) {
    int idx = blockIdx.x * blockDim.x + threadIdx.x;   // < 294912
    const int n = NB * NPARAM;
    int b = idx / NPARAM, p = idx - b * NPARAM;
    float s = b2[p];
#pragma unroll
    for (int kc = 0; kc < KSPLIT; kc++) s += g_part[idx + kc * n];

    int co = p / 288;       int r  = p - co * 288;
    int cin = r / 9;        int rr = r - cin * 9;
    int ky = rr / 3;        int kx = rr - ky * 3;
    int k  = (ky * 3 + kx) * 32 + cin;

    g_wb[(size_t)b * WB_ELEMS + co * WB_ROW + k] = __float2half_rn(s);
}

// ---------------------------------------------------------------------------
// Kernel 4: warp-mma conv, fp16. CTA = (b, 8 out rows, 64 out cols), 1024
// threads = 32 warps: warp = (y-row 0..7, x-quarter 0..3 of 16 cols).
// A = x split into fp16 hi/lo (2 passes), B = weights single fp16.
// Per (q,h): 4 ldsm (Ah, Al, B0, B1) -> 8 mma.
// ---------------------------------------------------------------------------
#define XT_XS 40                 // cin stride (elems) per x — bank-safe pad
#define XT_YS (66 * XT_XS)       // 2640 elems
#define XT_ELEMS (10 * XT_YS)    // 26400 elems
#define XT_BYTES (XT_ELEMS * 2)
#define SB_ROWB (WB_ROW * 2)     // 592 B per co row
#define SB_BYTES (32 * SB_ROWB)  // 18944 B (single half)
#define CONV_SMEM (2 * XT_BYTES + SB_BYTES)   // 124544 B

__global__ void __launch_bounds__(1024, 1)
conv_kernel(const float* __restrict__ x, float* __restrict__ out) {
    extern __shared__ unsigned char smem[];
    __half* s_xhi = (__half*)smem;
    __half* s_xlo = (__half*)(smem + XT_BYTES);
    uint4*  s_b4  = (uint4*)(smem + 2 * XT_BYTES);

    int t = threadIdx.x, lane = t & 31, w = t >> 5;
    int b   = blockIdx.z;
    int y0  = blockIdx.y * 8;
    int x0g = blockIdx.x * 64;

    // ---- B copy (pre-laid-out fp16) ----
    {
        const uint4* src = (const uint4*)(g_wb + (size_t)b * WB_ELEMS);
        for (int i = t; i < SB_BYTES / 16; i += 1024) s_b4[i] = src[i];
    }

    // ---- x tile: [y 0..9][x 0..65][cin], fp16 hi/lo ----
    for (int pp = w; pp < 320; pp += 32) {       // pp = cin*10 + y
        int cin = pp / 10, y = pp - cin * 10;
        int gy = y0 - 1 + y;
        bool yv = (gy >= 0) && (gy < HWD);
        const float* row = x + (((size_t)b * 32 + cin) * HWD + gy) * HWD;
        for (int xx = lane; xx < 66; xx += 32) {
            int gx = x0g - 1 + xx;
            float v = (yv && gx >= 0 && gx < HWD) ? row[gx] : 0.0f;
            __half hi = __float2half_rn(v);
            __half lo = __float2half_rn(v - __half2float(hi));
            int off = y * XT_YS + xx * XT_XS + cin;
            s_xhi[off] = hi;
            s_xlo[off] = lo;
        }
    }
    __syncthreads();

    uint32_t XHI = smem_to_u32(smem);
    uint32_t BHI = XHI + 2 * XT_BYTES;

    int yw = w >> 2;             // out row within slab (0..7)
    int xq = w & 3;              // x quarter (0..3), 16 cols each

    // lane-dependent ldmatrix address parts (validated mapping)
    uint32_t aoff = (uint32_t)(lane & 15) * (XT_XS * 2) +
                    (uint32_t)(lane >> 4) * 16u;          // row = x, k8 half
    uint32_t boff = (uint32_t)((((lane >> 4) & 1) * 8) + (lane & 7)) * SB_ROWB +
                    (uint32_t)((lane >> 3) & 1) * 16u;    // row = co, k8 half

    float d[4][4];
#pragma unroll
    for (int j = 0; j < 4; j++)
#pragma unroll
        for (int c = 0; c < 4; c++) d[j][c] = 0.0f;

    uint32_t awarp = XHI + aoff + (uint32_t)yw * (XT_YS * 2) +
                     (uint32_t)xq * (16 * XT_XS * 2);
    uint32_t bwarp = BHI + boff;

#pragma unroll 3
    for (int q = 0; q < 9; q++) {
        int ky = q / 3, kx = q - ky * 3;
        uint32_t aq = awarp + (uint32_t)ky * (XT_YS * 2) +
                      (uint32_t)kx * (XT_XS * 2);
        uint32_t bq = bwarp + (uint32_t)q * 64u;
#pragma unroll
        for (int h = 0; h < 2; h++) {
            uint32_t Ah[4], Al[4], B0[4], B1[4];
            ldsm_x4(Ah, aq + h * 32u);
            ldsm_x4(Al, aq + h * 32u + XT_BYTES);
            ldsm_x4(B0, bq + h * 32u);
            ldsm_x4(B1, bq + h * 32u + 16u * SB_ROWB);
            // hi pass
            mma_f16(d[0], Ah, B0[0], B0[1]);
            mma_f16(d[1], Ah, B0[2], B0[3]);
            mma_f16(d[2], Ah, B1[0], B1[1]);
            mma_f16(d[3], Ah, B1[2], B1[3]);
            // lo pass
            mma_f16(d[0], Al, B0[0], B0[1]);
            mma_f16(d[1], Al, B0[2], B0[3]);
            mma_f16(d[2], Al, B1[0], B1[1]);
            mma_f16(d[3], Al, B1[2], B1[3]);
        }
    }

    // ---- epilogue: D frag (row = x offset, col = co offset) -> out ----
    int g  = lane >> 2;
    int tg = lane & 3;
    int yo = y0 + yw;
    int xo = x0g + xq * 16 + g;
#pragma unroll
    for (int j = 0; j < 4; j++) {
        int co = j * 8 + tg * 2;
        float* p0 = out + (((size_t)(b * 32 + co)) * HWD + yo) * HWD + xo;
        p0[0]             = d[j][0];
        p0[HWD * HWD]     = d[j][1];
        p0[8]             = d[j][2];
        p0[HWD * HWD + 8] = d[j][3];
    }
}

// ---------------------------------------------------------------------------
extern "C" void kernel_launch(void* const* d_in, const int* in_sizes, int n_in,
                              void* d_out, int out_size) {
    const float* x    = (const float*)d_in[0];
    const float* cond = (const float*)d_in[1];
    const float* W1   = (const float*)d_in[2];
    const float* b1   = (const float*)d_in[3];
    const float* W2   = (const float*)d_in[4];
    const float* b2   = (const float*)d_in[5];
    float* out = (float*)d_out;

    cudaFuncSetAttribute(conv_kernel,
                         cudaFuncAttributeMaxDynamicSharedMemorySize, CONV_SMEM);

    mlp1_kernel<<<(HIDD * NB) / 256, 256>>>(cond, W1, b1);
    gemm2_kernel<<<dim3(NPARAM / 128, KSPLIT), 256>>>(W2);
    reduce_kernel<<<(NB * NPARAM) / 256, 256>>>(b2);
    conv_kernel<<<dim3(2, 16, NB), 1024, CONV_SMEM>>>(x, out);
}

// round 8
// speedup vs baseline: 2.2346x; 1.0558x over previous
#include <cuda_runtime.h>
#include <cuda_fp16.h>
#include <cstdint>

#define NB   32
#define HWD  128
#define CONDD 256
#define HIDD 4608
#define NPARAM 9216
#define KSPLIT 16
#define KCHUNK 288             // HIDD / KSPLIT

// Scratch (device globals: allocation-free rule)
__device__ float g_ht[HIDD * NB];
__device__ float g_part[KSPLIT * NB * NPARAM];
// per-sample conv weights, single fp16: [b][co 32][k 296 padded]
#define WB_ROW   296
#define WB_ELEMS (32 * WB_ROW)              // 9472 per sample
__device__ __align__(16) __half g_wb[NB * WB_ELEMS];

typedef unsigned long long u64;

// ---------------------------------------------------------------------------
// f32x2 helpers (gemm2 only)
// ---------------------------------------------------------------------------
__device__ __forceinline__ u64 pack2(float lo, float hi) {
    u64 r; asm("mov.b64 %0, {%1, %2};" : "=l"(r) : "f"(lo), "f"(hi)); return r;
}
__device__ __forceinline__ u64 splat2(float v) { return pack2(v, v); }
__device__ __forceinline__ u64 fma2(u64 a, u64 b, u64 c) {
    u64 d; asm("fma.rn.f32x2 %0, %1, %2, %3;" : "=l"(d) : "l"(a), "l"(b), "l"(c));
    return d;
}
__device__ __forceinline__ float2 unpack2(u64 v) {
    float2 r; asm("mov.b64 {%0, %1}, %2;" : "=f"(r.x), "=f"(r.y) : "l"(v));
    return r;
}

__device__ __forceinline__ uint32_t smem_to_u32(const void* p) {
    uint32_t a;
    asm("{ .reg .u64 t; cvta.to.shared.u64 t, %1; cvt.u32.u64 %0, t; }"
        : "=r"(a) : "l"(p));
    return a;
}

// ---------------------------------------------------------------------------
// warp-mma helpers (sm_80+ features: valid on plain sm_103 target)
// ---------------------------------------------------------------------------
__device__ __forceinline__ void ldsm_x4(uint32_t r[4], uint32_t addr) {
    asm volatile("ldmatrix.sync.aligned.m8n8.x4.shared.b16 {%0,%1,%2,%3}, [%4];"
        : "=r"(r[0]), "=r"(r[1]), "=r"(r[2]), "=r"(r[3]) : "r"(addr));
}
__device__ __forceinline__ void mma_f16(float d[4], const uint32_t a[4],
                                        uint32_t b0, uint32_t b1) {
    asm volatile(
        "mma.sync.aligned.m16n8k16.row.col.f32.f16.f16.f32 "
        "{%0,%1,%2,%3}, {%4,%5,%6,%7}, {%8,%9}, {%0,%1,%2,%3};"
        : "+f"(d[0]), "+f"(d[1]), "+f"(d[2]), "+f"(d[3])
        : "r"(a[0]), "r"(a[1]), "r"(a[2]), "r"(a[3]), "r"(b0), "r"(b1));
}

// ---------------------------------------------------------------------------
// Kernel 1: h = relu(cond @ W1^T + b1) -> ht[hid][b]
// ---------------------------------------------------------------------------
__global__ void mlp1_kernel(const float* __restrict__ cond,
                            const float* __restrict__ W1,
                            const float* __restrict__ b1) {
    int idx = blockIdx.x * blockDim.x + threadIdx.x;
    int hid = idx >> 5;
    int b   = idx & 31;
    const float4* c4 = (const float4*)(cond + b * CONDD);
    const float4* w4 = (const float4*)(W1 + (size_t)hid * CONDD);
    float acc = b1[hid];
#pragma unroll 8
    for (int i = 0; i < CONDD / 4; i++) {
        float4 cv = c4[i]; float4 wv = w4[i];
        acc += cv.x * wv.x + cv.y * wv.y + cv.z * wv.z + cv.w * wv.w;
    }
    g_ht[hid * 32 + b] = fmaxf(acc, 0.0f);
}

// ---------------------------------------------------------------------------
// Kernel 2: gemm2 k-split partials (f32x2, KSPLIT=16) — unchanged
// ---------------------------------------------------------------------------
__global__ void gemm2_kernel(const float* __restrict__ W2) {
    __shared__ float s_h[32 * 32];
    __shared__ float s_w[32 * 132];

    int t = threadIdx.x;
    int pbase = blockIdx.x * 128;
    int kc    = blockIdx.y;
    int b0 = (t & 7) * 4;
    int p0 = (t >> 3) * 4;

    u64 acc2[4][2];
#pragma unroll
    for (int i = 0; i < 4; i++) { acc2[i][0] = 0; acc2[i][1] = 0; }

    const float4* ht4 = (const float4*)g_ht;
    const float4* W24 = (const float4*)W2;

    int lh_k = t >> 3, lh_c4 = t & 7;
    int lw_p[4], lw_k4[4];
#pragma unroll
    for (int i = 0; i < 4; i++) {
        int j = t + i * 256; lw_p[i] = j >> 3; lw_k4[i] = j & 7;
    }

    int kbase = kc * KCHUNK;
    float4 rh = ht4[(kbase + lh_k) * 8 + lh_c4];
    float4 rw[4];
#pragma unroll
    for (int i = 0; i < 4; i++)
        rw[i] = W24[(size_t)(pbase + lw_p[i]) * 1152 + (kbase >> 2) + lw_k4[i]];

    for (int ks = 0; ks < KCHUNK; ks += 32) {
        __syncthreads();
        ((float4*)s_h)[t] = rh;
#pragma unroll
        for (int i = 0; i < 4; i++) {
            int p = lw_p[i], k4 = lw_k4[i];
            s_w[(k4 * 4 + 0) * 132 + p] = rw[i].x;
            s_w[(k4 * 4 + 1) * 132 + p] = rw[i].y;
            s_w[(k4 * 4 + 2) * 132 + p] = rw[i].z;
            s_w[(k4 * 4 + 3) * 132 + p] = rw[i].w;
        }
        __syncthreads();

        if (ks + 32 < KCHUNK) {
            int kn = kc * KCHUNK + ks + 32;
            rh = ht4[(kn + lh_k) * 8 + lh_c4];
#pragma unroll
            for (int i = 0; i < 4; i++)
                rw[i] = W24[(size_t)(pbase + lw_p[i]) * 1152 + (kn >> 2) + lw_k4[i]];
        }

#pragma unroll
        for (int kk = 0; kk < 32; kk++) {
            float4 hv = *(const float4*)&s_h[kk * 32 + b0];
            u64 w01 = *(const u64*)&s_w[kk * 132 + p0];
            u64 w23 = *(const u64*)&s_w[kk * 132 + p0 + 2];
            u64 hs0 = splat2(hv.x), hs1 = splat2(hv.y);
            u64 hs2 = splat2(hv.z), hs3 = splat2(hv.w);
            acc2[0][0] = fma2(hs0, w01, acc2[0][0]);
            acc2[0][1] = fma2(hs0, w23, acc2[0][1]);
            acc2[1][0] = fma2(hs1, w01, acc2[1][0]);
            acc2[1][1] = fma2(hs1, w23, acc2[1][1]);
            acc2[2][0] = fma2(hs2, w01, acc2[2][0]);
            acc2[2][1] = fma2(hs2, w23, acc2[2][1]);
            acc2[3][0] = fma2(hs3, w01, acc2[3][0]);
            acc2[3][1] = fma2(hs3, w23, acc2[3][1]);
        }
    }

    float* dst = g_part + (size_t)kc * (NB * NPARAM);
#pragma unroll
    for (int i = 0; i < 4; i++) {
        float2 lo = unpack2(acc2[i][0]);
        float2 hi = unpack2(acc2[i][1]);
        *(float4*)&dst[(size_t)(b0 + i) * NPARAM + pbase + p0] =
            make_float4(lo.x, lo.y, hi.x, hi.y);
    }
}

// ---------------------------------------------------------------------------
// Kernel 3: reduce partials + bias -> single fp16 weights [b][co][k]
// ---------------------------------------------------------------------------
__global__ void reduce_kernel(const float* __restrict__ b2) {
    int idx = blockIdx.x * blockDim.x + threadIdx.x;   // < 294912
    const int n = NB * NPARAM;
    int b = idx / NPARAM, p = idx - b * NPARAM;
    float s = b2[p];
#pragma unroll
    for (int kc = 0; kc < KSPLIT; kc++) s += g_part[idx + kc * n];

    int co = p / 288;       int r  = p - co * 288;
    int cin = r / 9;        int rr = r - cin * 9;
    int ky = rr / 3;        int kx = rr - ky * 3;
    int k  = (ky * 3 + kx) * 32 + cin;

    g_wb[(size_t)b * WB_ELEMS + co * WB_ROW + k] = __float2half_rn(s);
}

// ---------------------------------------------------------------------------
// Kernel 4: warp-mma conv, single-fp16 A and B. CTA = (b, 16 out rows,
// 64 out cols), 1024 threads = 32 warps: warp = (y 0..15, x-half 0..1).
// Warp owns 2 mtiles (16 x-cols each) x 4 ntiles; per (q,h): 4 ldsm
// (A0, A1, B0, B1) -> 8 mma, B frags reused across both mtiles.
// ---------------------------------------------------------------------------
#define XT_XS 40                 // cin stride (elems) per x — bank-safe pad
#define XT_YS (66 * XT_XS)       // 2640 elems per y row
#define XT_ROWS 18               // 16 out rows + halo
#define XT_ELEMS (XT_ROWS * XT_YS)
#define XT_BYTES (XT_ELEMS * 2)  // 95040 B
#define SB_ROWB (WB_ROW * 2)     // 592 B per co row
#define SB_BYTES (32 * SB_ROWB)  // 18944 B
#define CONV_SMEM (XT_BYTES + SB_BYTES)   // 113984 B

__global__ void __launch_bounds__(1024, 1)
conv_kernel(const float* __restrict__ x, float* __restrict__ out) {
    extern __shared__ unsigned char smem[];
    __half* s_x  = (__half*)smem;
    uint4*  s_b4 = (uint4*)(smem + XT_BYTES);

    int t = threadIdx.x, lane = t & 31, w = t >> 5;
    int b   = blockIdx.z;
    int y0  = blockIdx.y * 16;
    int x0g = blockIdx.x * 64;

    // ---- B copy (pre-laid-out fp16) ----
    {
        const uint4* src = (const uint4*)(g_wb + (size_t)b * WB_ELEMS);
        for (int i = t; i < SB_BYTES / 16; i += 1024) s_b4[i] = src[i];
    }

    // ---- x tile: [y 0..17][x 0..65][cin], single fp16 ----
    for (int pp = w; pp < 32 * XT_ROWS; pp += 32) {   // pp = cin*18 + y
        int cin = pp / XT_ROWS, y = pp - cin * XT_ROWS;
        int gy = y0 - 1 + y;
        bool yv = (gy >= 0) && (gy < HWD);
        const float* row = x + (((size_t)b * 32 + cin) * HWD + gy) * HWD;
        for (int xx = lane; xx < 66; xx += 32) {
            int gx = x0g - 1 + xx;
            float v = (yv && gx >= 0 && gx < HWD) ? row[gx] : 0.0f;
            s_x[y * XT_YS + xx * XT_XS + cin] = __float2half_rn(v);
        }
    }
    __syncthreads();

    uint32_t XB = smem_to_u32(smem);
    uint32_t BB = XB + XT_BYTES;

    int yw = w >> 1;             // out row within slab (0..15)
    int xh = w & 1;              // x half (0..1), 32 cols each

    // lane-dependent ldmatrix address parts (validated mapping)
    uint32_t aoff = (uint32_t)(lane & 15) * (XT_XS * 2) +
                    (uint32_t)(lane >> 4) * 16u;          // row = x, k8 half
    uint32_t boff = (uint32_t)((((lane >> 4) & 1) * 8) + (lane & 7)) * SB_ROWB +
                    (uint32_t)((lane >> 3) & 1) * 16u;    // row = co, k8 half

    float d[2][4][4];
#pragma unroll
    for (int i = 0; i < 2; i++)
#pragma unroll
        for (int j = 0; j < 4; j++)
#pragma unroll
            for (int c = 0; c < 4; c++) d[i][j][c] = 0.0f;

    uint32_t awarp = XB + aoff + (uint32_t)yw * (XT_YS * 2) +
                     (uint32_t)xh * (32 * XT_XS * 2);
    uint32_t bwarp = BB + boff;

#pragma unroll 3
    for (int q = 0; q < 9; q++) {
        int ky = q / 3, kx = q - ky * 3;
        uint32_t aq = awarp + (uint32_t)ky * (XT_YS * 2) +
                      (uint32_t)kx * (XT_XS * 2);
        uint32_t bq = bwarp + (uint32_t)q * 64u;
#pragma unroll
        for (int h = 0; h < 2; h++) {
            uint32_t A0[4], A1[4], B0[4], B1[4];
            ldsm_x4(A0, aq + h * 32u);
            ldsm_x4(A1, aq + h * 32u + (16 * XT_XS * 2));
            ldsm_x4(B0, bq + h * 32u);
            ldsm_x4(B1, bq + h * 32u + 16u * SB_ROWB);
            mma_f16(d[0][0], A0, B0[0], B0[1]);
            mma_f16(d[0][1], A0, B0[2], B0[3]);
            mma_f16(d[0][2], A0, B1[0], B1[1]);
            mma_f16(d[0][3], A0, B1[2], B1[3]);
            mma_f16(d[1][0], A1, B0[0], B0[1]);
            mma_f16(d[1][1], A1, B0[2], B0[3]);
            mma_f16(d[1][2], A1, B1[0], B1[1]);
            mma_f16(d[1][3], A1, B1[2], B1[3]);
        }
    }

    // ---- epilogue: D frag (row = x offset, col = co offset) -> out ----
    int g  = lane >> 2;
    int tg = lane & 3;
    int yo = y0 + yw;
#pragma unroll
    for (int i = 0; i < 2; i++) {
        int xo = x0g + xh * 32 + i * 16 + g;
#pragma unroll
        for (int j = 0; j < 4; j++) {
            int co = j * 8 + tg * 2;
            float* p0 = out + (((size_t)(b * 32 + co)) * HWD + yo) * HWD + xo;
            p0[0]             = d[i][j][0];
            p0[HWD * HWD]     = d[i][j][1];
            p0[8]             = d[i][j][2];
            p0[HWD * HWD + 8] = d[i][j][3];
        }
    }
}

// ---------------------------------------------------------------------------
extern "C" void kernel_launch(void* const* d_in, const int* in_sizes, int n_in,
                              void* d_out, int out_size) {
    const float* x    = (const float*)d_in[0];
    const float* cond = (const float*)d_in[1];
    const float* W1   = (const float*)d_in[2];
    const float* b1   = (const float*)d_in[3];
    const float* W2   = (const float*)d_in[4];
    const float* b2   = (const float*)d_in[5];
    float* out = (float*)d_out;

    cudaFuncSetAttribute(conv_kernel,
                         cudaFuncAttributeMaxDynamicSharedMemorySize, CONV_SMEM);

    mlp1_kernel<<<(HIDD * NB) / 256, 256>>>(cond, W1, b1);
    gemm2_kernel<<<dim3(NPARAM / 128, KSPLIT), 256>>>(W2);
    reduce_kernel<<<(NB * NPARAM) / 256, 256>>>(b2);
    conv_kernel<<<dim3(2, 8, NB), 1024, CONV_SMEM>>>(x, out);
}

// round 9
// speedup vs baseline: 2.4970x; 1.1175x over previous
#include <cuda_runtime.h>
#include <cuda_fp16.h>
#include <cstdint>

#define NB   32
#define HWD  128
#define CONDD 256
#define HIDD 4608
#define NPARAM 9216
#define KSPLIT 16
#define KCHUNK 288             // HIDD / KSPLIT

// Scratch (device globals: allocation-free rule)
__device__ float g_ht[HIDD * NB];
__device__ float g_part[KSPLIT * NB * NPARAM];
// per-sample conv weights, single fp16: [b][co 32][k 296 padded]
#define WB_ROW   296
#define WB_ELEMS (32 * WB_ROW)              // 9472 per sample
__device__ __align__(16) __half g_wb[NB * WB_ELEMS];
// x converted to fp16, transposed: [b][y][x][cin]  (32 MB)
__device__ __align__(16) __half g_xh[(size_t)NB * HWD * HWD * 32];

typedef unsigned long long u64;

// ---------------------------------------------------------------------------
// f32x2 helpers (gemm2 only)
// ---------------------------------------------------------------------------
__device__ __forceinline__ u64 pack2(float lo, float hi) {
    u64 r; asm("mov.b64 %0, {%1, %2};" : "=l"(r) : "f"(lo), "f"(hi)); return r;
}
__device__ __forceinline__ u64 splat2(float v) { return pack2(v, v); }
__device__ __forceinline__ u64 fma2(u64 a, u64 b, u64 c) {
    u64 d; asm("fma.rn.f32x2 %0, %1, %2, %3;" : "=l"(d) : "l"(a), "l"(b), "l"(c));
    return d;
}
__device__ __forceinline__ float2 unpack2(u64 v) {
    float2 r; asm("mov.b64 {%0, %1}, %2;" : "=f"(r.x), "=f"(r.y) : "l"(v));
    return r;
}

__device__ __forceinline__ uint32_t smem_to_u32(const void* p) {
    uint32_t a;
    asm("{ .reg .u64 t; cvta.to.shared.u64 t, %1; cvt.u32.u64 %0, t; }"
        : "=r"(a) : "l"(p));
    return a;
}

// ---------------------------------------------------------------------------
// warp-mma helpers (sm_80+ features: valid on plain sm_103 target)
// ---------------------------------------------------------------------------
__device__ __forceinline__ void ldsm_x4(uint32_t r[4], uint32_t addr) {
    asm volatile("ldmatrix.sync.aligned.m8n8.x4.shared.b16 {%0,%1,%2,%3}, [%4];"
        : "=r"(r[0]), "=r"(r[1]), "=r"(r[2]), "=r"(r[3]) : "r"(addr));
}
__device__ __forceinline__ void mma_f16(float d[4], const uint32_t a[4],
                                        uint32_t b0, uint32_t b1) {
    asm volatile(
        "mma.sync.aligned.m16n8k16.row.col.f32.f16.f16.f32 "
        "{%0,%1,%2,%3}, {%4,%5,%6,%7}, {%8,%9}, {%0,%1,%2,%3};"
        : "+f"(d[0]), "+f"(d[1]), "+f"(d[2]), "+f"(d[3])
        : "r"(a[0]), "r"(a[1]), "r"(a[2]), "r"(a[3]), "r"(b0), "r"(b1));
}

// ---------------------------------------------------------------------------
// Kernel 0: x fp32 [b][cin][y][x] -> g_xh fp16 [b][y][x][cin]
// ---------------------------------------------------------------------------
__global__ void xprep_kernel(const float* __restrict__ x) {
    int b = blockIdx.y, y = blockIdx.x, t = threadIdx.x;
    __half* dst = g_xh + ((size_t)(b * HWD + y) * HWD) * 32;
    for (int idx = t; idx < 2048; idx += 256) {
        int cp = idx >> 7;           // cin pair 0..15
        int xx = idx & 127;
        float v0 = x[(((size_t)b * 32 + 2 * cp)     * HWD + y) * HWD + xx];
        float v1 = x[(((size_t)b * 32 + 2 * cp + 1) * HWD + y) * HWD + xx];
        *(__half2*)(dst + (size_t)xx * 32 + 2 * cp) = __floats2half2_rn(v0, v1);
    }
}

// ---------------------------------------------------------------------------
// Kernel 1: h = relu(cond @ W1^T + b1) -> ht[hid][b]
// ---------------------------------------------------------------------------
__global__ void mlp1_kernel(const float* __restrict__ cond,
                            const float* __restrict__ W1,
                            const float* __restrict__ b1) {
    int idx = blockIdx.x * blockDim.x + threadIdx.x;
    int hid = idx >> 5;
    int b   = idx & 31;
    const float4* c4 = (const float4*)(cond + b * CONDD);
    const float4* w4 = (const float4*)(W1 + (size_t)hid * CONDD);
    float acc = b1[hid];
#pragma unroll 8
    for (int i = 0; i < CONDD / 4; i++) {
        float4 cv = c4[i]; float4 wv = w4[i];
        acc += cv.x * wv.x + cv.y * wv.y + cv.z * wv.z + cv.w * wv.w;
    }
    g_ht[hid * 32 + b] = fmaxf(acc, 0.0f);
}

// ---------------------------------------------------------------------------
// Kernel 2: gemm2 k-split partials (f32x2, KSPLIT=16) — unchanged
// ---------------------------------------------------------------------------
__global__ void gemm2_kernel(const float* __restrict__ W2) {
    __shared__ float s_h[32 * 32];
    __shared__ float s_w[32 * 132];

    int t = threadIdx.x;
    int pbase = blockIdx.x * 128;
    int kc    = blockIdx.y;
    int b0 = (t & 7) * 4;
    int p0 = (t >> 3) * 4;

    u64 acc2[4][2];
#pragma unroll
    for (int i = 0; i < 4; i++) { acc2[i][0] = 0; acc2[i][1] = 0; }

    const float4* ht4 = (const float4*)g_ht;
    const float4* W24 = (const float4*)W2;

    int lh_k = t >> 3, lh_c4 = t & 7;
    int lw_p[4], lw_k4[4];
#pragma unroll
    for (int i = 0; i < 4; i++) {
        int j = t + i * 256; lw_p[i] = j >> 3; lw_k4[i] = j & 7;
    }

    int kbase = kc * KCHUNK;
    float4 rh = ht4[(kbase + lh_k) * 8 + lh_c4];
    float4 rw[4];
#pragma unroll
    for (int i = 0; i < 4; i++)
        rw[i] = W24[(size_t)(pbase + lw_p[i]) * 1152 + (kbase >> 2) + lw_k4[i]];

    for (int ks = 0; ks < KCHUNK; ks += 32) {
        __syncthreads();
        ((float4*)s_h)[t] = rh;
#pragma unroll
        for (int i = 0; i < 4; i++) {
            int p = lw_p[i], k4 = lw_k4[i];
            s_w[(k4 * 4 + 0) * 132 + p] = rw[i].x;
            s_w[(k4 * 4 + 1) * 132 + p] = rw[i].y;
            s_w[(k4 * 4 + 2) * 132 + p] = rw[i].z;
            s_w[(k4 * 4 + 3) * 132 + p] = rw[i].w;
        }
        __syncthreads();

        if (ks + 32 < KCHUNK) {
            int kn = kc * KCHUNK + ks + 32;
            rh = ht4[(kn + lh_k) * 8 + lh_c4];
#pragma unroll
            for (int i = 0; i < 4; i++)
                rw[i] = W24[(size_t)(pbase + lw_p[i]) * 1152 + (kn >> 2) + lw_k4[i]];
        }

#pragma unroll
        for (int kk = 0; kk < 32; kk++) {
            float4 hv = *(const float4*)&s_h[kk * 32 + b0];
            u64 w01 = *(const u64*)&s_w[kk * 132 + p0];
            u64 w23 = *(const u64*)&s_w[kk * 132 + p0 + 2];
            u64 hs0 = splat2(hv.x), hs1 = splat2(hv.y);
            u64 hs2 = splat2(hv.z), hs3 = splat2(hv.w);
            acc2[0][0] = fma2(hs0, w01, acc2[0][0]);
            acc2[0][1] = fma2(hs0, w23, acc2[0][1]);
            acc2[1][0] = fma2(hs1, w01, acc2[1][0]);
            acc2[1][1] = fma2(hs1, w23, acc2[1][1]);
            acc2[2][0] = fma2(hs2, w01, acc2[2][0]);
            acc2[2][1] = fma2(hs2, w23, acc2[2][1]);
            acc2[3][0] = fma2(hs3, w01, acc2[3][0]);
            acc2[3][1] = fma2(hs3, w23, acc2[3][1]);
        }
    }

    float* dst = g_part + (size_t)kc * (NB * NPARAM);
#pragma unroll
    for (int i = 0; i < 4; i++) {
        float2 lo = unpack2(acc2[i][0]);
        float2 hi = unpack2(acc2[i][1]);
        *(float4*)&dst[(size_t)(b0 + i) * NPARAM + pbase + p0] =
            make_float4(lo.x, lo.y, hi.x, hi.y);
    }
}

// ---------------------------------------------------------------------------
// Kernel 3: reduce partials + bias -> single fp16 weights [b][co][k]
// ---------------------------------------------------------------------------
__global__ void reduce_kernel(const float* __restrict__ b2) {
    int idx = blockIdx.x * blockDim.x + threadIdx.x;   // < 294912
    const int n = NB * NPARAM;
    int b = idx / NPARAM, p = idx - b * NPARAM;
    float s = b2[p];
#pragma unroll
    for (int kc = 0; kc < KSPLIT; kc++) s += g_part[idx + kc * n];

    int co = p / 288;       int r  = p - co * 288;
    int cin = r / 9;        int rr = r - cin * 9;
    int ky = rr / 3;        int kx = rr - ky * 3;
    int k  = (ky * 3 + kx) * 32 + cin;

    g_wb[(size_t)b * WB_ELEMS + co * WB_ROW + k] = __float2half_rn(s);
}

// ---------------------------------------------------------------------------
// Kernel 4: warp-mma conv, fp16. CTA = (b, 16 out rows, 64 out cols), 1024
// threads = 32 warps: warp = (y 0..15, x-half 0..1), 2 mtiles x 4 ntiles.
// x tile now a pure vectorized copy from pre-converted g_xh.
// ---------------------------------------------------------------------------
#define XT_XS 40                 // cin stride (elems) per x — bank-safe pad
#define XT_YS (66 * XT_XS)       // 2640 elems per y row
#define XT_ROWS 18               // 16 out rows + halo
#define XT_ELEMS (XT_ROWS * XT_YS)
#define XT_BYTES (XT_ELEMS * 2)  // 95040 B
#define SB_ROWB (WB_ROW * 2)     // 592 B per co row
#define SB_BYTES (32 * SB_ROWB)  // 18944 B
#define CONV_SMEM (XT_BYTES + SB_BYTES)   // 113984 B

__global__ void __launch_bounds__(1024, 1)
conv_kernel(float* __restrict__ out) {
    extern __shared__ unsigned char smem[];
    uint4* s_b4 = (uint4*)(smem + XT_BYTES);

    int t = threadIdx.x, lane = t & 31, w = t >> 5;
    int b   = blockIdx.z;
    int y0  = blockIdx.y * 16;
    int x0g = blockIdx.x * 64;

    // ---- B copy (pre-laid-out fp16) ----
    {
        const uint4* src = (const uint4*)(g_wb + (size_t)b * WB_ELEMS);
        for (int i = t; i < SB_BYTES / 16; i += 1024) s_b4[i] = src[i];
    }

    // ---- x tile: vectorized copy, [y 0..17][x 0..65][cin 0..31] fp16 ----
    {
        const __half* xsrc = g_xh + (size_t)b * (HWD * HWD * 32);
        for (int idx = t; idx < XT_ROWS * 66 * 4; idx += 1024) {
            int row = idx >> 2, c4 = idx & 3;
            int y  = row / 66, xx = row - y * 66;
            int gy = y0 - 1 + y, gx = x0g - 1 + xx;
            uint4 v = make_uint4(0, 0, 0, 0);
            if (gy >= 0 && gy < HWD && gx >= 0 && gx < HWD)
                v = *(const uint4*)(xsrc + ((size_t)gy * HWD + gx) * 32 + c4 * 8);
            *(uint4*)(smem + (size_t)(y * XT_YS + xx * XT_XS) * 2 + c4 * 16) = v;
        }
    }
    __syncthreads();

    uint32_t XB = smem_to_u32(smem);
    uint32_t BB = XB + XT_BYTES;

    int yw = w >> 1;             // out row within slab (0..15)
    int xh = w & 1;              // x half (0..1), 32 cols each

    // lane-dependent ldmatrix address parts (validated mapping)
    uint32_t aoff = (uint32_t)(lane & 15) * (XT_XS * 2) +
                    (uint32_t)(lane >> 4) * 16u;          // row = x, k8 half
    uint32_t boff = (uint32_t)((((lane >> 4) & 1) * 8) + (lane & 7)) * SB_ROWB +
                    (uint32_t)((lane >> 3) & 1) * 16u;    // row = co, k8 half

    float d[2][4][4];
#pragma unroll
    for (int i = 0; i < 2; i++)
#pragma unroll
        for (int j = 0; j < 4; j++)
#pragma unroll
            for (int c = 0; c < 4; c++) d[i][j][c] = 0.0f;

    uint32_t awarp = XB + aoff + (uint32_t)yw * (XT_YS * 2) +
                     (uint32_t)xh * (32 * XT_XS * 2);
    uint32_t bwarp = BB + boff;

#pragma unroll 3
    for (int q = 0; q < 9; q++) {
        int ky = q / 3, kx = q - ky * 3;
        uint32_t aq = awarp + (uint32_t)ky * (XT_YS * 2) +
                      (uint32_t)kx * (XT_XS * 2);
        uint32_t bq = bwarp + (uint32_t)q * 64u;
#pragma unroll
        for (int h = 0; h < 2; h++) {
            uint32_t A0[4], A1[4], B0[4], B1[4];
            ldsm_x4(A0, aq + h * 32u);
            ldsm_x4(A1, aq + h * 32u + (16 * XT_XS * 2));
            ldsm_x4(B0, bq + h * 32u);
            ldsm_x4(B1, bq + h * 32u + 16u * SB_ROWB);
            mma_f16(d[0][0], A0, B0[0], B0[1]);
            mma_f16(d[0][1], A0, B0[2], B0[3]);
            mma_f16(d[0][2], A0, B1[0], B1[1]);
            mma_f16(d[0][3], A0, B1[2], B1[3]);
            mma_f16(d[1][0], A1, B0[0], B0[1]);
            mma_f16(d[1][1], A1, B0[2], B0[3]);
            mma_f16(d[1][2], A1, B1[0], B1[1]);
            mma_f16(d[1][3], A1, B1[2], B1[3]);
        }
    }

    // ---- epilogue: D frag (row = x offset, col = co offset) -> out ----
    int g  = lane >> 2;
    int tg = lane & 3;
    int yo = y0 + yw;
#pragma unroll
    for (int i = 0; i < 2; i++) {
        int xo = x0g + xh * 32 + i * 16 + g;
#pragma unroll
        for (int j = 0; j < 4; j++) {
            int co = j * 8 + tg * 2;
            float* p0 = out + (((size_t)(b * 32 + co)) * HWD + yo) * HWD + xo;
            p0[0]             = d[i][j][0];
            p0[HWD * HWD]     = d[i][j][1];
            p0[8]             = d[i][j][2];
            p0[HWD * HWD + 8] = d[i][j][3];
        }
    }
}

// ---------------------------------------------------------------------------
extern "C" void kernel_launch(void* const* d_in, const int* in_sizes, int n_in,
                              void* d_out, int out_size) {
    const float* x    = (const float*)d_in[0];
    const float* cond = (const float*)d_in[1];
    const float* W1   = (const float*)d_in[2];
    const float* b1   = (const float*)d_in[3];
    const float* W2   = (const float*)d_in[4];
    const float* b2   = (const float*)d_in[5];
    float* out = (float*)d_out;

    cudaFuncSetAttribute(conv_kernel,
                         cudaFuncAttributeMaxDynamicSharedMemorySize, CONV_SMEM);

    xprep_kernel<<<dim3(HWD, NB), 256>>>(x);
    mlp1_kernel<<<(HIDD * NB) / 256, 256>>>(cond, W1, b1);
    gemm2_kernel<<<dim3(NPARAM / 128, KSPLIT), 256>>>(W2);
    reduce_kernel<<<(NB * NPARAM) / 256, 256>>>(b2);
    conv_kernel<<<dim3(2, 8, NB), 1024, CONV_SMEM>>>(out);
}

// round 10
// speedup vs baseline: 3.1127x; 1.2465x over previous
#include <cuda_runtime.h>
#include <cuda_fp16.h>
#include <cstdint>

#define NB   32
#define HWD  128
#define CONDD 256
#define HIDD 4608
#define NPARAM 9216

// Scratch (device globals: allocation-free rule)
// h fp16, [b][k] layout for MMA A tiles
__device__ __align__(16) __half g_hh[NB * HIDD];
// per-sample conv weights, single fp16: [b][co 32][k 296 padded]
#define WB_ROW   296
#define WB_ELEMS (32 * WB_ROW)              // 9472 per sample
__device__ __align__(16) __half g_wb[NB * WB_ELEMS];
// x converted to fp16, transposed: [b][y][x][cin]  (32 MB)
__device__ __align__(16) __half g_xh[(size_t)NB * HWD * HWD * 32];

__device__ __forceinline__ uint32_t smem_to_u32(const void* p) {
    uint32_t a;
    asm("{ .reg .u64 t; cvta.to.shared.u64 t, %1; cvt.u32.u64 %0, t; }"
        : "=r"(a) : "l"(p));
    return a;
}

// ---------------------------------------------------------------------------
// warp-mma helpers (sm_80+ features: valid on plain sm_103 target)
// ---------------------------------------------------------------------------
__device__ __forceinline__ void ldsm_x4(uint32_t r[4], uint32_t addr) {
    asm volatile("ldmatrix.sync.aligned.m8n8.x4.shared.b16 {%0,%1,%2,%3}, [%4];"
        : "=r"(r[0]), "=r"(r[1]), "=r"(r[2]), "=r"(r[3]) : "r"(addr));
}
__device__ __forceinline__ void mma_f16(float d[4], const uint32_t a[4],
                                        uint32_t b0, uint32_t b1) {
    asm volatile(
        "mma.sync.aligned.m16n8k16.row.col.f32.f16.f16.f32 "
        "{%0,%1,%2,%3}, {%4,%5,%6,%7}, {%8,%9}, {%0,%1,%2,%3};"
        : "+f"(d[0]), "+f"(d[1]), "+f"(d[2]), "+f"(d[3])
        : "r"(a[0]), "r"(a[1]), "r"(a[2]), "r"(a[3]), "r"(b0), "r"(b1));
}

// ---------------------------------------------------------------------------
// Kernel 0: x fp32 [b][cin][y][x] -> g_xh fp16 [b][y][x][cin]
// ---------------------------------------------------------------------------
__global__ void xprep_kernel(const float* __restrict__ x) {
    int b = blockIdx.y, y = blockIdx.x, t = threadIdx.x;
    __half* dst = g_xh + ((size_t)(b * HWD + y) * HWD) * 32;
    for (int idx = t; idx < 2048; idx += 256) {
        int cp = idx >> 7;           // cin pair 0..15
        int xx = idx & 127;
        float v0 = x[(((size_t)b * 32 + 2 * cp)     * HWD + y) * HWD + xx];
        float v1 = x[(((size_t)b * 32 + 2 * cp + 1) * HWD + y) * HWD + xx];
        *(__half2*)(dst + (size_t)xx * 32 + 2 * cp) = __floats2half2_rn(v0, v1);
    }
}

// ---------------------------------------------------------------------------
// Kernel 1: h = relu(cond @ W1^T + b1) -> g_hh fp16 [b][hid]
// ---------------------------------------------------------------------------
__global__ void mlp1_kernel(const float* __restrict__ cond,
                            const float* __restrict__ W1,
                            const float* __restrict__ b1) {
    int idx = blockIdx.x * blockDim.x + threadIdx.x;
    int hid = idx >> 5;
    int b   = idx & 31;
    const float4* c4 = (const float4*)(cond + b * CONDD);
    const float4* w4 = (const float4*)(W1 + (size_t)hid * CONDD);
    float acc = b1[hid];
#pragma unroll 8
    for (int i = 0; i < CONDD / 4; i++) {
        float4 cv = c4[i]; float4 wv = w4[i];
        acc += cv.x * wv.x + cv.y * wv.y + cv.z * wv.z + cv.w * wv.w;
    }
    g_hh[b * HIDD + hid] = __float2half_rn(fmaxf(acc, 0.0f));
}

// ---------------------------------------------------------------------------
// Kernel 2: tensor-core gemm2 + fused bias/layout epilogue -> g_wb fp16.
// w[b 32, p 9216] = h[32, K=4608] @ W2[p, K]^T + b2.
// CTA = 64 p-rows, K-chunks of 128, W2 converted f32->fp16 in-register.
// 8 warps = (m-half 0..1) x (n16 slice 0..3). Grid 144.
// ---------------------------------------------------------------------------
#define GP 64
#define GK 128
#define TST 272                  // smem tile row stride (256B data + 16B pad)
#define SB_OFF 0                 // B tile: 64 rows
#define SA_OFF (64 * TST)        // A tile: 32 rows
#define G2_SMEM (96 * TST)       // 26112 B

__global__ void __launch_bounds__(256, 1)
gemm2_kernel(const float* __restrict__ W2, const float* __restrict__ b2) {
    __shared__ __align__(16) unsigned char sm[G2_SMEM];

    int t = threadIdx.x, lane = t & 31, w = t >> 5;
    int pbase = blockIdx.x * GP;

    // per-thread load slots
    int brow = t >> 2;                 // B tile row (p) 0..63
    int bf4  = t & 3;                  // float4 column group
    const float4* W24 = (const float4*)(W2 + (size_t)(pbase + brow) * HIDD);
    int arow0 = t >> 4,        ac0 = t & 15;          // A slots (idx t, t+256)
    int arow1 = (t + 256) >> 4, ac1 = (t + 256) & 15;

    // prefetch chunk 0
    float4 rw[8]; uint4 rh[2];
#pragma unroll
    for (int i = 0; i < 8; i++) rw[i] = W24[bf4 + 4 * i];
    rh[0] = *(const uint4*)(g_hh + (size_t)arow0 * HIDD + ac0 * 8);
    rh[1] = *(const uint4*)(g_hh + (size_t)arow1 * HIDD + ac1 * 8);

    uint32_t SMB = smem_to_u32(sm);
    int mh = w & 1;                    // m-half (b 0-15 / 16-31)
    int nw = w >> 1;                   // n16 slice 0..3

    uint32_t Abase = SMB + SA_OFF +
        (uint32_t)(mh * 16 + (lane & 15)) * TST + (uint32_t)(lane >> 4) * 16u;
    uint32_t Bbase = SMB + SB_OFF +
        (uint32_t)(nw * 16 + (((lane >> 4) & 1) * 8) + (lane & 7)) * TST +
        (uint32_t)((lane >> 3) & 1) * 16u;

    float d0[4] = {0, 0, 0, 0}, d1[4] = {0, 0, 0, 0};

    for (int kc = 0; kc < HIDD / GK; kc++) {
        __syncthreads();
        // store prefetched tiles (convert W2 f32 -> fp16)
#pragma unroll
        for (int i = 0; i < 8; i++) {
            __half2 h0 = __floats2half2_rn(rw[i].x, rw[i].y);
            __half2 h1 = __floats2half2_rn(rw[i].z, rw[i].w);
            uint32_t u0 = *(uint32_t*)&h0, u1 = *(uint32_t*)&h1;
            uint32_t addr = SMB + SB_OFF + (uint32_t)brow * TST +
                            (uint32_t)(bf4 + 4 * i) * 8u;
            asm volatile("st.shared.v2.b32 [%0], {%1, %2};"
                         :: "r"(addr), "r"(u0), "r"(u1) : "memory");
        }
        {
            uint32_t a0 = SMB + SA_OFF + (uint32_t)arow0 * TST + ac0 * 16u;
            uint32_t a1 = SMB + SA_OFF + (uint32_t)arow1 * TST + ac1 * 16u;
            asm volatile("st.shared.v4.b32 [%0], {%1, %2, %3, %4};"
                :: "r"(a0), "r"(rh[0].x), "r"(rh[0].y), "r"(rh[0].z), "r"(rh[0].w) : "memory");
            asm volatile("st.shared.v4.b32 [%0], {%1, %2, %3, %4};"
                :: "r"(a1), "r"(rh[1].x), "r"(rh[1].y), "r"(rh[1].z), "r"(rh[1].w) : "memory");
        }
        __syncthreads();

        // prefetch next chunk
        if (kc + 1 < HIDD / GK) {
            int ko = (kc + 1) * 32;    // float4 offset within W2 row
#pragma unroll
            for (int i = 0; i < 8; i++) rw[i] = W24[ko + bf4 + 4 * i];
            int kh = (kc + 1) * GK;
            rh[0] = *(const uint4*)(g_hh + (size_t)arow0 * HIDD + kh + ac0 * 8);
            rh[1] = *(const uint4*)(g_hh + (size_t)arow1 * HIDD + kh + ac1 * 8);
        }

        // compute: 8 k16 steps
#pragma unroll
        for (int ks = 0; ks < 8; ks++) {
            uint32_t A[4], B[4];
            ldsm_x4(A, Abase + (uint32_t)ks * 32u);
            ldsm_x4(B, Bbase + (uint32_t)ks * 32u);
            mma_f16(d0, A, B[0], B[1]);
            mma_f16(d1, A, B[2], B[3]);
        }
    }

    // ---- fused epilogue: bias, p -> (co, k) scatter, fp16 store ----
    int g  = lane >> 2;
    int tg = lane & 3;
#pragma unroll
    for (int j = 0; j < 2; j++) {
        const float* dj = (j == 0) ? d0 : d1;
#pragma unroll
        for (int c = 0; c < 2; c++) {
            int p = pbase + nw * 16 + j * 8 + tg * 2 + c;
            float bias = b2[p];
            int co = p / 288;
            int r  = p - co * 288;
            int cin = r / 9;
            int rr  = r - cin * 9;
            int k   = rr * 32 + cin;
            int b0 = mh * 16 + g;
            g_wb[(size_t)b0 * WB_ELEMS + co * WB_ROW + k] =
                __float2half_rn(dj[c] + bias);
            g_wb[(size_t)(b0 + 8) * WB_ELEMS + co * WB_ROW + k] =
                __float2half_rn(dj[2 + c] + bias);
        }
    }
}

// ---------------------------------------------------------------------------
// Kernel 3: warp-mma conv, fp16 (unchanged from R9).
// ---------------------------------------------------------------------------
#define XT_XS 40
#define XT_YS (66 * XT_XS)
#define XT_ROWS 18
#define XT_ELEMS (XT_ROWS * XT_YS)
#define XT_BYTES (XT_ELEMS * 2)  // 95040 B
#define SB_ROWB (WB_ROW * 2)     // 592 B per co row
#define SB_BYTES (32 * SB_ROWB)  // 18944 B
#define CONV_SMEM (XT_BYTES + SB_BYTES)   // 113984 B

__global__ void __launch_bounds__(1024, 1)
conv_kernel(float* __restrict__ out) {
    extern __shared__ unsigned char smem[];
    uint4* s_b4 = (uint4*)(smem + XT_BYTES);

    int t = threadIdx.x, lane = t & 31, w = t >> 5;
    int b   = blockIdx.z;
    int y0  = blockIdx.y * 16;
    int x0g = blockIdx.x * 64;

    {
        const uint4* src = (const uint4*)(g_wb + (size_t)b * WB_ELEMS);
        for (int i = t; i < SB_BYTES / 16; i += 1024) s_b4[i] = src[i];
    }
    {
        const __half* xsrc = g_xh + (size_t)b * (HWD * HWD * 32);
        for (int idx = t; idx < XT_ROWS * 66 * 4; idx += 1024) {
            int row = idx >> 2, c4 = idx & 3;
            int y  = row / 66, xx = row - y * 66;
            int gy = y0 - 1 + y, gx = x0g - 1 + xx;
            uint4 v = make_uint4(0, 0, 0, 0);
            if (gy >= 0 && gy < HWD && gx >= 0 && gx < HWD)
                v = *(const uint4*)(xsrc + ((size_t)gy * HWD + gx) * 32 + c4 * 8);
            *(uint4*)(smem + (size_t)(y * XT_YS + xx * XT_XS) * 2 + c4 * 16) = v;
        }
    }
    __syncthreads();

    uint32_t XB = smem_to_u32(smem);
    uint32_t BB = XB + XT_BYTES;

    int yw = w >> 1;
    int xh = w & 1;

    uint32_t aoff = (uint32_t)(lane & 15) * (XT_XS * 2) +
                    (uint32_t)(lane >> 4) * 16u;
    uint32_t boff = (uint32_t)((((lane >> 4) & 1) * 8) + (lane & 7)) * SB_ROWB +
                    (uint32_t)((lane >> 3) & 1) * 16u;

    float d[2][4][4];
#pragma unroll
    for (int i = 0; i < 2; i++)
#pragma unroll
        for (int j = 0; j < 4; j++)
#pragma unroll
            for (int c = 0; c < 4; c++) d[i][j][c] = 0.0f;

    uint32_t awarp = XB + aoff + (uint32_t)yw * (XT_YS * 2) +
                     (uint32_t)xh * (32 * XT_XS * 2);
    uint32_t bwarp = BB + boff;

#pragma unroll 3
    for (int q = 0; q < 9; q++) {
        int ky = q / 3, kx = q - ky * 3;
        uint32_t aq = awarp + (uint32_t)ky * (XT_YS * 2) +
                      (uint32_t)kx * (XT_XS * 2);
        uint32_t bq = bwarp + (uint32_t)q * 64u;
#pragma unroll
        for (int h = 0; h < 2; h++) {
            uint32_t A0[4], A1[4], B0[4], B1[4];
            ldsm_x4(A0, aq + h * 32u);
            ldsm_x4(A1, aq + h * 32u + (16 * XT_XS * 2));
            ldsm_x4(B0, bq + h * 32u);
            ldsm_x4(B1, bq + h * 32u + 16u * SB_ROWB);
            mma_f16(d[0][0], A0, B0[0], B0[1]);
            mma_f16(d[0][1], A0, B0[2], B0[3]);
            mma_f16(d[0][2], A0, B1[0], B1[1]);
            mma_f16(d[0][3], A0, B1[2], B1[3]);
            mma_f16(d[1][0], A1, B0[0], B0[1]);
            mma_f16(d[1][1], A1, B0[2], B0[3]);
            mma_f16(d[1][2], A1, B1[0], B1[1]);
            mma_f16(d[1][3], A1, B1[2], B1[3]);
        }
    }

    int g  = lane >> 2;
    int tg = lane & 3;
    int yo = y0 + yw;
#pragma unroll
    for (int i = 0; i < 2; i++) {
        int xo = x0g + xh * 32 + i * 16 + g;
#pragma unroll
        for (int j = 0; j < 4; j++) {
            int co = j * 8 + tg * 2;
            float* p0 = out + (((size_t)(b * 32 + co)) * HWD + yo) * HWD + xo;
            p0[0]             = d[i][j][0];
            p0[HWD * HWD]     = d[i][j][1];
            p0[8]             = d[i][j][2];
            p0[HWD * HWD + 8] = d[i][j][3];
        }
    }
}

// ---------------------------------------------------------------------------
extern "C" void kernel_launch(void* const* d_in, const int* in_sizes, int n_in,
                              void* d_out, int out_size) {
    const float* x    = (const float*)d_in[0];
    const float* cond = (const float*)d_in[1];
    const float* W1   = (const float*)d_in[2];
    const float* b1   = (const float*)d_in[3];
    const float* W2   = (const float*)d_in[4];
    const float* b2   = (const float*)d_in[5];
    float* out = (float*)d_out;

    cudaFuncSetAttribute(conv_kernel,
                         cudaFuncAttributeMaxDynamicSharedMemorySize, CONV_SMEM);

    xprep_kernel<<<dim3(HWD, NB), 256>>>(x);
    mlp1_kernel<<<(HIDD * NB) / 256, 256>>>(cond, W1, b1);
    gemm2_kernel<<<NPARAM / GP, 256>>>(W2, b2);
    conv_kernel<<<dim3(2, 8, NB), 1024, CONV_SMEM>>>(out);
}

// round 11
// speedup vs baseline: 3.5613x; 1.1441x over previous
#include <cuda_runtime.h>
#include <cuda_fp16.h>
#include <cstdint>

#define NB   32
#define HWD  128
#define CONDD 256
#define HIDD 4608
#define NPARAM 9216

// Scratch (device globals: allocation-free rule)
// h fp16, [b][k] layout for MMA A tiles
__device__ __align__(16) __half g_hh[NB * HIDD];
// per-sample conv weights, single fp16: [b][co 32][k 296 padded]
#define WB_ROW   296
#define WB_ELEMS (32 * WB_ROW)              // 9472 per sample
__device__ __align__(16) __half g_wb[NB * WB_ELEMS];
// x fp16, layout [b][c4 0..3][y][x][cin8]  (32 MB) — coalesced prep writes
__device__ __align__(16) __half g_xh[(size_t)NB * 4 * HWD * HWD * 8];

__device__ __forceinline__ uint32_t smem_to_u32(const void* p) {
    uint32_t a;
    asm("{ .reg .u64 t; cvta.to.shared.u64 t, %1; cvt.u32.u64 %0, t; }"
        : "=r"(a) : "l"(p));
    return a;
}

// ---------------------------------------------------------------------------
// warp-mma helpers (sm_80+ features: valid on plain sm_103 target)
// ---------------------------------------------------------------------------
__device__ __forceinline__ void ldsm_x4(uint32_t r[4], uint32_t addr) {
    asm volatile("ldmatrix.sync.aligned.m8n8.x4.shared.b16 {%0,%1,%2,%3}, [%4];"
        : "=r"(r[0]), "=r"(r[1]), "=r"(r[2]), "=r"(r[3]) : "r"(addr));
}
__device__ __forceinline__ void mma_f16(float d[4], const uint32_t a[4],
                                        uint32_t b0, uint32_t b1) {
    asm volatile(
        "mma.sync.aligned.m16n8k16.row.col.f32.f16.f16.f32 "
        "{%0,%1,%2,%3}, {%4,%5,%6,%7}, {%8,%9}, {%0,%1,%2,%3};"
        : "+f"(d[0]), "+f"(d[1]), "+f"(d[2]), "+f"(d[3])
        : "r"(a[0]), "r"(a[1]), "r"(a[2]), "r"(a[3]), "r"(b0), "r"(b1));
}

// ---------------------------------------------------------------------------
// Kernel 0: x fp32 [b][cin][y][x] -> g_xh fp16 [b][c4][y][x][cin8]
// Reads coalesced (fixed cin, consecutive x), writes one contiguous uint4.
// ---------------------------------------------------------------------------
__global__ void xprep_kernel(const float* __restrict__ x) {
    int b = blockIdx.y, y = blockIdx.x, t = threadIdx.x;   // 512 threads
    int c4 = t >> 7;          // cin octet 0..3
    int xx = t & 127;
    float v[8];
#pragma unroll
    for (int i = 0; i < 8; i++)
        v[i] = x[(((size_t)b * 32 + c4 * 8 + i) * HWD + y) * HWD + xx];
    __half2 h[4];
#pragma unroll
    for (int i = 0; i < 4; i++)
        h[i] = __floats2half2_rn(v[2 * i], v[2 * i + 1]);
    uint4 o = make_uint4(*(uint32_t*)&h[0], *(uint32_t*)&h[1],
                         *(uint32_t*)&h[2], *(uint32_t*)&h[3]);
    *(uint4*)(g_xh + ((((size_t)b * 4 + c4) * HWD + y) * HWD + xx) * 8) = o;
}

// ---------------------------------------------------------------------------
// Kernel 1: h = relu(cond @ W1^T + b1) -> g_hh fp16 [b][hid]
// ---------------------------------------------------------------------------
__global__ void mlp1_kernel(const float* __restrict__ cond,
                            const float* __restrict__ W1,
                            const float* __restrict__ b1) {
    int idx = blockIdx.x * blockDim.x + threadIdx.x;
    int hid = idx >> 5;
    int b   = idx & 31;
    const float4* c4 = (const float4*)(cond + b * CONDD);
    const float4* w4 = (const float4*)(W1 + (size_t)hid * CONDD);
    float acc = b1[hid];
#pragma unroll 8
    for (int i = 0; i < CONDD / 4; i++) {
        float4 cv = c4[i]; float4 wv = w4[i];
        acc += cv.x * wv.x + cv.y * wv.y + cv.z * wv.z + cv.w * wv.w;
    }
    g_hh[b * HIDD + hid] = __float2half_rn(fmaxf(acc, 0.0f));
}

// ---------------------------------------------------------------------------
// Kernel 2: tensor-core gemm2 + fused bias/layout epilogue -> g_wb fp16.
// w[b 32, p 9216] = h[32, K=4608] @ W2[p, K]^T + b2.
// CTA = 32 p-rows, 128 threads (4 warps = mh x nw), grid 288 (~2 CTA/SM).
// ---------------------------------------------------------------------------
#define GP 32
#define GK 128
#define TST 272                  // smem tile row stride (256B data + 16B pad)
#define SB_OFF 0                 // B tile: 32 rows
#define SA_OFF (32 * TST)        // A tile: 32 rows
#define G2_SMEM (64 * TST)       // 17408 B

__global__ void __launch_bounds__(128, 2)
gemm2_kernel(const float* __restrict__ W2, const float* __restrict__ b2) {
    __shared__ __align__(16) unsigned char sm[G2_SMEM];

    int t = threadIdx.x, lane = t & 31, w = t >> 5;
    int pbase = blockIdx.x * GP;

    // per-thread load slots
    int brow = t >> 2;                 // B tile row (p) 0..31
    int bf4  = t & 3;                  // float4 column group
    const float4* W24 = (const float4*)(W2 + (size_t)(pbase + brow) * HIDD);
    int arow[4], ac[4];                // A slots (idx t + 128*i)
#pragma unroll
    for (int i = 0; i < 4; i++) {
        int j = t + 128 * i; arow[i] = j >> 4; ac[i] = j & 15;
    }

    // prefetch chunk 0
    float4 rw[8]; uint4 rh[4];
#pragma unroll
    for (int i = 0; i < 8; i++) rw[i] = W24[bf4 + 4 * i];
#pragma unroll
    for (int i = 0; i < 4; i++)
        rh[i] = *(const uint4*)(g_hh + (size_t)arow[i] * HIDD + ac[i] * 8);

    uint32_t SMB = smem_to_u32(sm);
    int mh = w & 1;                    // m-half (b 0-15 / 16-31)
    int nw = w >> 1;                   // n16 slice 0..1

    uint32_t Abase = SMB + SA_OFF +
        (uint32_t)(mh * 16 + (lane & 15)) * TST + (uint32_t)(lane >> 4) * 16u;
    uint32_t Bbase = SMB + SB_OFF +
        (uint32_t)(nw * 16 + (((lane >> 4) & 1) * 8) + (lane & 7)) * TST +
        (uint32_t)((lane >> 3) & 1) * 16u;

    float d0[4] = {0, 0, 0, 0}, d1[4] = {0, 0, 0, 0};

    for (int kc = 0; kc < HIDD / GK; kc++) {
        __syncthreads();
        // store prefetched tiles (convert W2 f32 -> fp16)
#pragma unroll
        for (int i = 0; i < 8; i++) {
            __half2 h0 = __floats2half2_rn(rw[i].x, rw[i].y);
            __half2 h1 = __floats2half2_rn(rw[i].z, rw[i].w);
            uint32_t u0 = *(uint32_t*)&h0, u1 = *(uint32_t*)&h1;
            uint32_t addr = SMB + SB_OFF + (uint32_t)brow * TST +
                            (uint32_t)(bf4 + 4 * i) * 8u;
            asm volatile("st.shared.v2.b32 [%0], {%1, %2};"
                         :: "r"(addr), "r"(u0), "r"(u1) : "memory");
        }
#pragma unroll
        for (int i = 0; i < 4; i++) {
            uint32_t a0 = SMB + SA_OFF + (uint32_t)arow[i] * TST + ac[i] * 16u;
            asm volatile("st.shared.v4.b32 [%0], {%1, %2, %3, %4};"
                :: "r"(a0), "r"(rh[i].x), "r"(rh[i].y), "r"(rh[i].z), "r"(rh[i].w) : "memory");
        }
        __syncthreads();

        // prefetch next chunk
        if (kc + 1 < HIDD / GK) {
            int ko = (kc + 1) * 32;    // float4 offset within W2 row
#pragma unroll
            for (int i = 0; i < 8; i++) rw[i] = W24[ko + bf4 + 4 * i];
            int kh = (kc + 1) * GK;
#pragma unroll
            for (int i = 0; i < 4; i++)
                rh[i] = *(const uint4*)(g_hh + (size_t)arow[i] * HIDD + kh + ac[i] * 8);
        }

        // compute: 8 k16 steps
#pragma unroll
        for (int ks = 0; ks < 8; ks++) {
            uint32_t A[4], B[4];
            ldsm_x4(A, Abase + (uint32_t)ks * 32u);
            ldsm_x4(B, Bbase + (uint32_t)ks * 32u);
            mma_f16(d0, A, B[0], B[1]);
            mma_f16(d1, A, B[2], B[3]);
        }
    }

    // ---- fused epilogue: bias, p -> (co, k) scatter, fp16 store ----
    int g  = lane >> 2;
    int tg = lane & 3;
#pragma unroll
    for (int j = 0; j < 2; j++) {
        const float* dj = (j == 0) ? d0 : d1;
#pragma unroll
        for (int c = 0; c < 2; c++) {
            int p = pbase + nw * 16 + j * 8 + tg * 2 + c;
            float bias = b2[p];
            int co = p / 288;
            int r  = p - co * 288;
            int cin = r / 9;
            int rr  = r - cin * 9;
            int k   = rr * 32 + cin;
            int b0 = mh * 16 + g;
            g_wb[(size_t)b0 * WB_ELEMS + co * WB_ROW + k] =
                __float2half_rn(dj[c] + bias);
            g_wb[(size_t)(b0 + 8) * WB_ELEMS + co * WB_ROW + k] =
                __float2half_rn(dj[2 + c] + bias);
        }
    }
}

// ---------------------------------------------------------------------------
// Kernel 3: warp-mma conv, fp16 (MMA loop unchanged; tile copy re-addressed
// for the new g_xh layout).
// ---------------------------------------------------------------------------
#define XT_XS 40
#define XT_YS (66 * XT_XS)
#define XT_ROWS 18
#define XT_ELEMS (XT_ROWS * XT_YS)
#define XT_BYTES (XT_ELEMS * 2)  // 95040 B
#define SB_ROWB (WB_ROW * 2)     // 592 B per co row
#define SB_BYTES (32 * SB_ROWB)  // 18944 B
#define CONV_SMEM (XT_BYTES + SB_BYTES)   // 113984 B

__global__ void __launch_bounds__(1024, 1)
conv_kernel(float* __restrict__ out) {
    extern __shared__ unsigned char smem[];
    uint4* s_b4 = (uint4*)(smem + XT_BYTES);

    int t = threadIdx.x, lane = t & 31, w = t >> 5;
    int b   = blockIdx.z;
    int y0  = blockIdx.y * 16;
    int x0g = blockIdx.x * 64;

    {
        const uint4* src = (const uint4*)(g_wb + (size_t)b * WB_ELEMS);
        for (int i = t; i < SB_BYTES / 16; i += 1024) s_b4[i] = src[i];
    }
    {
        const __half* xsrc = g_xh + (size_t)b * (4 * HWD * HWD * 8);
        for (int idx = t; idx < XT_ROWS * 66 * 4; idx += 1024) {
            int row = idx >> 2, c4 = idx & 3;
            int y  = row / 66, xx = row - y * 66;
            int gy = y0 - 1 + y, gx = x0g - 1 + xx;
            uint4 v = make_uint4(0, 0, 0, 0);
            if (gy >= 0 && gy < HWD && gx >= 0 && gx < HWD)
                v = *(const uint4*)(xsrc + (((size_t)c4 * HWD + gy) * HWD + gx) * 8);
            *(uint4*)(smem + (size_t)(y * XT_YS + xx * XT_XS) * 2 + c4 * 16) = v;
        }
    }
    __syncthreads();

    uint32_t XB = smem_to_u32(smem);
    uint32_t BB = XB + XT_BYTES;

    int yw = w >> 1;
    int xh = w & 1;

    uint32_t aoff = (uint32_t)(lane & 15) * (XT_XS * 2) +
                    (uint32_t)(lane >> 4) * 16u;
    uint32_t boff = (uint32_t)((((lane >> 4) & 1) * 8) + (lane & 7)) * SB_ROWB +
                    (uint32_t)((lane >> 3) & 1) * 16u;

    float d[2][4][4];
#pragma unroll
    for (int i = 0; i < 2; i++)
#pragma unroll
        for (int j = 0; j < 4; j++)
#pragma unroll
            for (int c = 0; c < 4; c++) d[i][j][c] = 0.0f;

    uint32_t awarp = XB + aoff + (uint32_t)yw * (XT_YS * 2) +
                     (uint32_t)xh * (32 * XT_XS * 2);
    uint32_t bwarp = BB + boff;

#pragma unroll 3
    for (int q = 0; q < 9; q++) {
        int ky = q / 3, kx = q - ky * 3;
        uint32_t aq = awarp + (uint32_t)ky * (XT_YS * 2) +
                      (uint32_t)kx * (XT_XS * 2);
        uint32_t bq = bwarp + (uint32_t)q * 64u;
#pragma unroll
        for (int h = 0; h < 2; h++) {
            uint32_t A0[4], A1[4], B0[4], B1[4];
            ldsm_x4(A0, aq + h * 32u);
            ldsm_x4(A1, aq + h * 32u + (16 * XT_XS * 2));
            ldsm_x4(B0, bq + h * 32u);
            ldsm_x4(B1, bq + h * 32u + 16u * SB_ROWB);
            mma_f16(d[0][0], A0, B0[0], B0[1]);
            mma_f16(d[0][1], A0, B0[2], B0[3]);
            mma_f16(d[0][2], A0, B1[0], B1[1]);
            mma_f16(d[0][3], A0, B1[2], B1[3]);
            mma_f16(d[1][0], A1, B0[0], B0[1]);
            mma_f16(d[1][1], A1, B0[2], B0[3]);
            mma_f16(d[1][2], A1, B1[0], B1[1]);
            mma_f16(d[1][3], A1, B1[2], B1[3]);
        }
    }

    int g  = lane >> 2;
    int tg = lane & 3;
    int yo = y0 + yw;
#pragma unroll
    for (int i = 0; i < 2; i++) {
        int xo = x0g + xh * 32 + i * 16 + g;
#pragma unroll
        for (int j = 0; j < 4; j++) {
            int co = j * 8 + tg * 2;
            float* p0 = out + (((size_t)(b * 32 + co)) * HWD + yo) * HWD + xo;
            p0[0]             = d[i][j][0];
            p0[HWD * HWD]     = d[i][j][1];
            p0[8]             = d[i][j][2];
            p0[HWD * HWD + 8] = d[i][j][3];
        }
    }
}

// ---------------------------------------------------------------------------
extern "C" void kernel_launch(void* const* d_in, const int* in_sizes, int n_in,
                              void* d_out, int out_size) {
    const float* x    = (const float*)d_in[0];
    const float* cond = (const float*)d_in[1];
    const float* W1   = (const float*)d_in[2];
    const float* b1   = (const float*)d_in[3];
    const float* W2   = (const float*)d_in[4];
    const float* b2   = (const float*)d_in[5];
    float* out = (float*)d_out;

    cudaFuncSetAttribute(conv_kernel,
                         cudaFuncAttributeMaxDynamicSharedMemorySize, CONV_SMEM);

    xprep_kernel<<<dim3(HWD, NB), 512>>>(x);
    mlp1_kernel<<<(HIDD * NB) / 256, 256>>>(cond, W1, b1);
    gemm2_kernel<<<NPARAM / GP, 128>>>(W2, b2);
    conv_kernel<<<dim3(2, 8, NB), 1024, CONV_SMEM>>>(out);
}